// round 5
// baseline (speedup 1.0000x reference)
#include <cuda_runtime.h>
#include <cstdint>

#define NUM_B 2
#define SEQ   2048
#define DIM   1024
#define NH    16
#define HD    64
#define M_ROWS (NUM_B*SEQ)      // 4096
#define N_QKV  (3*DIM)          // 3072
#define KDIM   DIM              // 1024

// Scratch (static device arrays — no runtime allocation)
__device__ float g_q  [(size_t)NUM_B*NH*SEQ*HD];
__device__ float g_k  [(size_t)NUM_B*NH*SEQ*HD];
__device__ float g_v  [(size_t)NUM_B*NH*SEQ*HD];
__device__ float g_att[(size_t)M_ROWS*DIM];
__device__ float g_wqt[(size_t)N_QKV*KDIM];   // W_qkv^T  [3072][1024]
__device__ float g_wot[(size_t)DIM*KDIM];     // W_o^T    [1024][1024]

// ---------------------------------------------------------------------------
// Helpers (sm_80-baseline PTX; validated R3/R4)
// ---------------------------------------------------------------------------
__device__ __forceinline__ float tf32f(float x) {
    float r;
    asm("cvt.rna.tf32.f32 %0, %1;" : "=f"(r) : "f"(x));
    return r;
}
__device__ __forceinline__ void split2(float x, float& h, float& l) {
    asm("cvt.rna.tf32.f32 %0, %1;" : "=f"(h) : "f"(x));
    float r = x - h;
    asm("cvt.rna.tf32.f32 %0, %1;" : "=f"(l) : "f"(r));
}
__device__ __forceinline__ void mma_tf32(float* d,
                                         uint32_t a0, uint32_t a1, uint32_t a2, uint32_t a3,
                                         uint32_t b0, uint32_t b1) {
    asm volatile(
        "mma.sync.aligned.m16n8k8.row.col.f32.tf32.tf32.f32 "
        "{%0,%1,%2,%3}, {%4,%5,%6,%7}, {%8,%9}, {%0,%1,%2,%3};"
        : "+f"(d[0]), "+f"(d[1]), "+f"(d[2]), "+f"(d[3])
        : "r"(a0), "r"(a1), "r"(a2), "r"(a3), "r"(b0), "r"(b1));
}
#define U(x) __float_as_uint(x)

// ---------------------------------------------------------------------------
// Weight transpose: src[R][C] -> dst[C][R]
// ---------------------------------------------------------------------------
__global__ void transpose32(const float* __restrict__ src, float* __restrict__ dst,
                            int R, int C) {
    __shared__ float tb[32][33];
    int bx = blockIdx.x * 32, by = blockIdx.y * 32;
    int x = threadIdx.x, y = threadIdx.y;
    #pragma unroll
    for (int i = 0; i < 32; i += 8)
        tb[y + i][x] = src[(size_t)(by + y + i) * C + bx + x];
    __syncthreads();
    #pragma unroll
    for (int i = 0; i < 32; i += 8)
        dst[(size_t)(bx + y + i) * R + by + x] = tb[x][y + i];
}

// ---------------------------------------------------------------------------
// 3xTF32 mma.sync GEMM v2: pre-split (hi,lo) interleaved smem, LDG-reg
// prefetch + double-buffered smem. 128x128 tile, K-chunk 16, 8 warps.
// ---------------------------------------------------------------------------
#define GK     16
#define NCH    (KDIM/GK)          // 64
#define GE     20                 // float2 per row (16 + 4 pad), GE%16==4
#define GROWF  (2*GE)             // 40 floats
#define GTILEF (128*GROWF)        // 5120 floats per operand
#define GBUF   (2*GTILEF)         // A+B one stage
#define GSMEM  (2*GBUF*(int)sizeof(float))   // 81920 B

__global__ __launch_bounds__(256, 2) void tf32_gemm(
    const float* __restrict__ A,    // [M][K] row-major
    const float* __restrict__ Bt,   // [N][K] row-major
    const float* __restrict__ bias,
    float* __restrict__ outp, int mode)
{
    extern __shared__ float smf[];
    const int t = threadIdx.x, wid = t >> 5, lane = t & 31;
    const int qr = lane >> 2, qc = lane & 3;
    const int m0 = blockIdx.y * 128, n0 = blockIdx.x * 128;
    const int wm = (wid & 3) * 32, wn = (wid >> 2) * 64;
    const int lrow = t >> 2, lk = (t & 3) * 4;

    const float* aptr = A  + (size_t)(m0 + lrow) * KDIM + lk;
    const float* bptr = Bt + (size_t)(n0 + lrow) * KDIM + lk;

    float acc[2][8][4];
    #pragma unroll
    for (int i = 0; i < 2; i++)
        #pragma unroll
        for (int j = 0; j < 8; j++)
            #pragma unroll
            for (int e = 0; e < 4; e++) acc[i][j][e] = 0.f;

    float4 ra0, ra1, rb0, rb1;

    auto LDG = [&](int c) {
        const float* ap = aptr + c * GK;
        ra0 = *(const float4*)ap;
        ra1 = *(const float4*)(ap + (size_t)64 * KDIM);
        const float* bp = bptr + c * GK;
        rb0 = *(const float4*)bp;
        rb1 = *(const float4*)(bp + (size_t)64 * KDIM);
    };
    auto STS1 = [&](float* dst, int row, float4 v) {
        float4 w0, w1;
        split2(v.x, w0.x, w0.y); split2(v.y, w0.z, w0.w);
        split2(v.z, w1.x, w1.y); split2(v.w, w1.z, w1.w);
        *(float4*)(dst + row * GROWF + 2 * lk)     = w0;
        *(float4*)(dst + row * GROWF + 2 * lk + 4) = w1;
    };
    auto STS = [&](int buf) {
        float* as = smf + buf * GBUF;
        float* bs = as + GTILEF;
        STS1(as, lrow,      ra0);
        STS1(as, lrow + 64, ra1);
        STS1(bs, lrow,      rb0);
        STS1(bs, lrow + 64, rb1);
    };

    LDG(0);
    STS(0);
    LDG(1);
    __syncthreads();

    for (int c = 0; c < NCH; c++) {
        if (c + 1 < NCH) STS((c + 1) & 1);
        if (c + 2 < NCH) LDG(c + 2);

        const float2* a2 = (const float2*)(smf + (c & 1) * GBUF);
        const float2* b2 = a2 + GTILEF / 2;

        #pragma unroll
        for (int ks = 0; ks < 2; ks++) {
            const int kk = ks * 8;
            float2 af[2][4];
            #pragma unroll
            for (int tm = 0; tm < 2; tm++) {
                const int mr = wm + tm * 16 + qr;
                af[tm][0] = a2[ mr      * GE + kk + qc];
                af[tm][1] = a2[(mr + 8) * GE + kk + qc];
                af[tm][2] = a2[ mr      * GE + kk + qc + 4];
                af[tm][3] = a2[(mr + 8) * GE + kk + qc + 4];
            }
            #pragma unroll
            for (int tn = 0; tn < 8; tn++) {
                const int nr = wn + tn * 8 + qr;
                const float2 bf0 = b2[nr * GE + kk + qc];
                const float2 bf1 = b2[nr * GE + kk + qc + 4];
                #pragma unroll
                for (int tm = 0; tm < 2; tm++) {
                    float* d = acc[tm][tn];
                    mma_tf32(d, U(af[tm][0].x), U(af[tm][1].x), U(af[tm][2].x), U(af[tm][3].x),
                             U(bf0.x), U(bf1.x));
                    mma_tf32(d, U(af[tm][0].x), U(af[tm][1].x), U(af[tm][2].x), U(af[tm][3].x),
                             U(bf0.y), U(bf1.y));
                    mma_tf32(d, U(af[tm][0].y), U(af[tm][1].y), U(af[tm][2].y), U(af[tm][3].y),
                             U(bf0.x), U(bf1.x));
                }
            }
        }
        __syncthreads();
    }

    // Epilogue (identical mapping to R3/R4)
    #pragma unroll
    for (int tm = 0; tm < 2; tm++) {
        const int r0 = m0 + wm + tm * 16 + qr;
        #pragma unroll
        for (int tn = 0; tn < 8; tn++) {
            const int col = n0 + wn + tn * 8 + qc * 2;
            const float bz0 = bias[col], bz1 = bias[col + 1];
            #pragma unroll
            for (int half = 0; half < 2; half++) {
                const int row = r0 + half * 8;
                const float v0 = acc[tm][tn][half * 2 + 0] + bz0;
                const float v1 = acc[tm][tn][half * 2 + 1] + bz1;
                if (mode == 0) {
                    const int bb = row >> 11, s = row & (SEQ - 1);
                    const int h = col / 192, r = col - h * 192;
                    const int part = r >> 6, dd = r & 63;
                    float* dst = (part == 0) ? g_q : (part == 1) ? g_k : g_v;
                    *(float2*)&dst[(((size_t)(bb * NH + h)) * SEQ + s) * HD + dd] =
                        make_float2(v0, v1);
                } else {
                    *(float2*)&outp[(size_t)row * DIM + col] = make_float2(v0, v1);
                }
            }
        }
    }
}

// ---------------------------------------------------------------------------
// Flash attention v2 (mma.sync tf32):
//  - Q fragments (x2 folded, hi/lo) hoisted to registers for the whole kernel
//  - K in smem as interleaved (hi,lo) float2, stride 68 float2 (conflict-free)
//  - V un-transposed, stride 72 floats (b-frag banks 8qc+qr: all distinct)
//  - Ps aliases the K plane after the S-loop
//  smem = 53504 B -> 3 CTAs/SM
// ---------------------------------------------------------------------------
#define KP2   68                  // Kp stride in float2
#define VSTR  72                  // Vs stride in floats
#define PSTR  68                  // Ps stride in floats
#define KP_F  (64*KP2*2)          // 8704 floats
#define VS_F  (64*VSTR)           // 4608 floats
#define FLASH_SMEM ((KP_F + VS_F + 64)*(int)sizeof(float))   // 53504 B

__global__ __launch_bounds__(128, 3) void flash_mma() {
    extern __shared__ float s[];
    float2* Kp2 = (float2*)s;              // [key][d] (hi,lo)
    float*  Vs  = s + KP_F;                // [key][d] tf32-rounded
    float*  ksq = s + KP_F + VS_F;         // [64]
    float*  Ps  = s;                       // alias Kp (dead after S-loop)

    const int t = threadIdx.x, lane = t & 31, w = t >> 5;
    const int qr = lane >> 2, qc = lane & 3;
    const int wm = w * 16;
    const int bh = blockIdx.y;
    const int s0 = blockIdx.x * 64;
    const size_t base = (size_t)bh * SEQ * HD;

    // --- Q fragments to registers (loop-invariant), x2 folded, hi/lo split ---
    uint32_t qah[8][4], qal[8][4];
    {
        const float* q0 = g_q + base + (size_t)(s0 + wm + qr) * HD;
        const float* q1 = q0 + 8 * HD;
        #pragma unroll
        for (int ks = 0; ks < 8; ks++) {
            const int d0 = ks * 8 + qc, d1 = d0 + 4;
            float h, l;
            split2(2.f * q0[d0], h, l); qah[ks][0] = U(h); qal[ks][0] = U(l);
            split2(2.f * q1[d0], h, l); qah[ks][1] = U(h); qal[ks][1] = U(l);
            split2(2.f * q0[d1], h, l); qah[ks][2] = U(h); qal[ks][2] = U(l);
            split2(2.f * q1[d1], h, l); qah[ks][3] = U(h); qal[ks][3] = U(l);
        }
    }

    float oacc[8][4];
    #pragma unroll
    for (int tn = 0; tn < 8; tn++)
        #pragma unroll
        for (int e = 0; e < 4; e++) oacc[tn][e] = 0.f;
    float m0r = -1e30f, m1r = -1e30f, l0r = 0.f, l1r = 0.f;

    for (int t0 = 0; t0 < SEQ; t0 += 64) {
        __syncthreads();   // prior-iter PV reads of Ps(Kp)/Vs done
        // --- load K (split, interleaved) + V (tf32, natural layout) ---
        #pragma unroll
        for (int i = 0; i < 8; i++) {
            const int li  = t + i * 128;
            const int row = li >> 4, c4 = (li & 15) << 2;
            const float4 kv = *(const float4*)(g_k + base + (size_t)(t0 + row) * HD + c4);
            float4 w0, w1;
            split2(kv.x, w0.x, w0.y); split2(kv.y, w0.z, w0.w);
            split2(kv.z, w1.x, w1.y); split2(kv.w, w1.z, w1.w);
            float* kdst = s + row * (2 * KP2) + 2 * c4;
            *(float4*)kdst       = w0;
            *(float4*)(kdst + 4) = w1;
            const float4 vv = *(const float4*)(g_v + base + (size_t)(t0 + row) * HD + c4);
            *(float4*)&Vs[row * VSTR + c4] =
                make_float4(tf32f(vv.x), tf32f(vv.y), tf32f(vv.z), tf32f(vv.w));
        }
        __syncthreads();

        // --- ksq[key] = |k|^2 (reconstruct hi+lo) ---
        {
            const int key = t >> 1, half = (t & 1) * 32;
            const float2* kr = Kp2 + key * KP2 + half;
            float ss = 0.f;
            #pragma unroll
            for (int j = 0; j < 32; j++) {
                const float2 hl = kr[j];
                const float kv = hl.x + hl.y;
                ss = fmaf(kv, kv, ss);
            }
            ss += __shfl_xor_sync(0xffffffffu, ss, 1);
            if (!(t & 1)) ksq[key] = ss;
        }
        __syncthreads();

        // --- S = (2Q).K^T  (3xTF32, Q from registers) ---
        float sacc[8][4];
        #pragma unroll
        for (int tn = 0; tn < 8; tn++)
            #pragma unroll
            for (int e = 0; e < 4; e++) sacc[tn][e] = 0.f;

        #pragma unroll
        for (int ks = 0; ks < 8; ks++) {
            #pragma unroll
            for (int tn = 0; tn < 8; tn++) {
                const float2 k0 = Kp2[(tn * 8 + qr) * KP2 + ks * 8 + qc];
                const float2 k1 = Kp2[(tn * 8 + qr) * KP2 + ks * 8 + qc + 4];
                float* d = sacc[tn];
                mma_tf32(d, qah[ks][0], qah[ks][1], qah[ks][2], qah[ks][3],
                         U(k0.x), U(k1.x));
                mma_tf32(d, qah[ks][0], qah[ks][1], qah[ks][2], qah[ks][3],
                         U(k0.y), U(k1.y));
                mma_tf32(d, qal[ks][0], qal[ks][1], qal[ks][2], qal[ks][3],
                         U(k0.x), U(k1.x));
            }
        }

        __syncthreads();   // all warps done reading Kp — safe to alias as Ps

        // --- softmax (rows wm+qr, wm+qr+8) ---
        float mx0 = -1e30f, mx1 = -1e30f;
        #pragma unroll
        for (int tn = 0; tn < 8; tn++) {
            const float k0 = ksq[tn * 8 + 2 * qc], k1 = ksq[tn * 8 + 2 * qc + 1];
            sacc[tn][0] -= k0; sacc[tn][1] -= k1;
            sacc[tn][2] -= k0; sacc[tn][3] -= k1;
            mx0 = fmaxf(mx0, fmaxf(sacc[tn][0], sacc[tn][1]));
            mx1 = fmaxf(mx1, fmaxf(sacc[tn][2], sacc[tn][3]));
        }
        #pragma unroll
        for (int off = 1; off <= 2; off <<= 1) {
            mx0 = fmaxf(mx0, __shfl_xor_sync(0xffffffffu, mx0, off));
            mx1 = fmaxf(mx1, __shfl_xor_sync(0xffffffffu, mx1, off));
        }
        const float mn0 = fmaxf(m0r, mx0), mn1 = fmaxf(m1r, mx1);
        const float a0 = __expf(m0r - mn0), a1 = __expf(m1r - mn1);
        m0r = mn0; m1r = mn1;

        float rs0 = 0.f, rs1 = 0.f;
        #pragma unroll
        for (int tn = 0; tn < 8; tn++) {
            const float p0 = __expf(sacc[tn][0] - mn0);
            const float p1 = __expf(sacc[tn][1] - mn0);
            const float p2 = __expf(sacc[tn][2] - mn1);
            const float p3 = __expf(sacc[tn][3] - mn1);
            rs0 += p0 + p1; rs1 += p2 + p3;
            *(float2*)&Ps[(wm + qr    ) * PSTR + tn * 8 + 2 * qc] =
                make_float2(tf32f(p0), tf32f(p1));
            *(float2*)&Ps[(wm + qr + 8) * PSTR + tn * 8 + 2 * qc] =
                make_float2(tf32f(p2), tf32f(p3));
        }
        #pragma unroll
        for (int off = 1; off <= 2; off <<= 1) {
            rs0 += __shfl_xor_sync(0xffffffffu, rs0, off);
            rs1 += __shfl_xor_sync(0xffffffffu, rs1, off);
        }
        l0r = l0r * a0 + rs0;
        l1r = l1r * a1 + rs1;
        #pragma unroll
        for (int tn = 0; tn < 8; tn++) {
            oacc[tn][0] *= a0; oacc[tn][1] *= a0;
            oacc[tn][2] *= a1; oacc[tn][3] *= a1;
        }
        __syncwarp();   // Ps rows are warp-private: order STS before LDS

        // --- O += P.V  (1xTF32; V natural layout) ---
        #pragma unroll
        for (int ks = 0; ks < 8; ks++) {
            const float* pp = Ps + (wm + qr) * PSTR + ks * 8 + qc;
            const uint32_t p0 = U(pp[0]);
            const uint32_t p1 = U(pp[8 * PSTR]);
            const uint32_t p2 = U(pp[4]);
            const uint32_t p3 = U(pp[8 * PSTR + 4]);
            #pragma unroll
            for (int tn = 0; tn < 8; tn++) {
                const float b0 = Vs[(ks * 8 + qc    ) * VSTR + tn * 8 + qr];
                const float b1 = Vs[(ks * 8 + qc + 4) * VSTR + tn * 8 + qr];
                mma_tf32(oacc[tn], p0, p1, p2, p3, U(b0), U(b1));
            }
        }
    }

    // --- epilogue: normalize, write g_att[B,S,D] (D = h*64 + d) ---
    const float inv0 = 1.f / l0r, inv1 = 1.f / l1r;
    const int b = bh >> 4, h = bh & 15;
    const int row0 = s0 + wm + qr, row1 = row0 + 8;
    #pragma unroll
    for (int tn = 0; tn < 8; tn++) {
        const int col = h * HD + tn * 8 + 2 * qc;
        *(float2*)&g_att[(size_t)(b * SEQ + row0) * DIM + col] =
            make_float2(oacc[tn][0] * inv0, oacc[tn][1] * inv0);
        *(float2*)&g_att[(size_t)(b * SEQ + row1) * DIM + col] =
            make_float2(oacc[tn][2] * inv1, oacc[tn][3] * inv1);
    }
}

// ---------------------------------------------------------------------------
extern "C" void kernel_launch(void* const* d_in, const int* in_sizes, int n_in,
                              void* d_out, int out_size) {
    (void)in_sizes; (void)n_in; (void)out_size;
    const float* x    = (const float*)d_in[0];
    const float* Wqkv = (const float*)d_in[1];
    const float* bqkv = (const float*)d_in[2];
    const float* Wo   = (const float*)d_in[3];
    const float* bo   = (const float*)d_in[4];
    float*       out  = (float*)d_out;

    float* wqt; cudaGetSymbolAddress((void**)&wqt, g_wqt);
    float* wot; cudaGetSymbolAddress((void**)&wot, g_wot);
    float* att; cudaGetSymbolAddress((void**)&att, g_att);

    cudaFuncSetAttribute(tf32_gemm, cudaFuncAttributeMaxDynamicSharedMemorySize, GSMEM);
    cudaFuncSetAttribute(flash_mma, cudaFuncAttributeMaxDynamicSharedMemorySize, FLASH_SMEM);

    transpose32<<<dim3(N_QKV/32, KDIM/32), dim3(32, 8)>>>(Wqkv, wqt, KDIM, N_QKV);
    transpose32<<<dim3(DIM/32,  KDIM/32), dim3(32, 8)>>>(Wo,   wot, KDIM, DIM);

    tf32_gemm<<<dim3(N_QKV/128, M_ROWS/128), 256, GSMEM>>>(x, wqt, bqkv, nullptr, 0);

    flash_mma<<<dim3(SEQ/64, NUM_B*NH), 128, FLASH_SMEM>>>();

    tf32_gemm<<<dim3(DIM/128, M_ROWS/128), 256, GSMEM>>>(att, wot, bo, out, 1);
}

// round 6
// speedup vs baseline: 1.1348x; 1.1348x over previous
#include <cuda_runtime.h>
#include <cstdint>

#define NUM_B 2
#define SEQ   2048
#define DIM   1024
#define NH    16
#define HD    64
#define M_ROWS (NUM_B*SEQ)      // 4096
#define N_QKV  (3*DIM)          // 3072
#define KDIM   DIM              // 1024
#define KCHUNK 32
#define NCHUNK (KDIM/KCHUNK)    // 32

#define LOG2E 1.4426950408889634f
#define C2LE  2.8853900817779268f   // 2*log2(e)

// Scratch (static device arrays — no runtime allocation)
__device__ float g_q  [(size_t)NUM_B*NH*SEQ*HD];
__device__ float g_k  [(size_t)NUM_B*NH*SEQ*HD];
__device__ float g_v  [(size_t)NUM_B*NH*SEQ*HD];
__device__ float g_att[(size_t)M_ROWS*DIM];
__device__ float g_wqt[(size_t)N_QKV*KDIM];
__device__ float g_wot[(size_t)DIM*KDIM];
// Packed operands for flash (written once by prep_pack)
__device__ float g_qp [(size_t)NUM_B*NH*SEQ*2*HD];   // 2c*q hi/lo packed
__device__ float g_kq [(size_t)NUM_B*NH*SEQ*2*HD];   // k hi/lo packed
__device__ float g_vp [(size_t)NUM_B*NH*(SEQ/2)*2*HD]; // v tf32, key-paired
__device__ float g_ksq[(size_t)NUM_B*NH*SEQ];        // log2e*|k|^2

// ---------------------------------------------------------------------------
// Helpers
// ---------------------------------------------------------------------------
__device__ __forceinline__ float tf32f(float x) {
    float r;
    asm("cvt.rna.tf32.f32 %0, %1;" : "=f"(r) : "f"(x));
    return r;
}
__device__ __forceinline__ float ex2f(float x) {
    float r;
    asm("ex2.approx.f32 %0, %1;" : "=f"(r) : "f"(x));
    return r;
}
__device__ __forceinline__ void split2(float x, float& h, float& l) {
    asm("cvt.rna.tf32.f32 %0, %1;" : "=f"(h) : "f"(x));
    float r = x - h;
    asm("cvt.rna.tf32.f32 %0, %1;" : "=f"(l) : "f"(r));
}
__device__ __forceinline__ void split_tf32(float x, uint32_t& hi, uint32_t& lo) {
    float h, l;
    split2(x, h, l);
    hi = __float_as_uint(h);
    lo = __float_as_uint(l);
}
__device__ __forceinline__ void mma_tf32(float* d,
                                         uint32_t a0, uint32_t a1, uint32_t a2, uint32_t a3,
                                         uint32_t b0, uint32_t b1) {
    asm volatile(
        "mma.sync.aligned.m16n8k8.row.col.f32.tf32.tf32.f32 "
        "{%0,%1,%2,%3}, {%4,%5,%6,%7}, {%8,%9}, {%0,%1,%2,%3};"
        : "+f"(d[0]), "+f"(d[1]), "+f"(d[2]), "+f"(d[3])
        : "r"(a0), "r"(a1), "r"(a2), "r"(a3), "r"(b0), "r"(b1));
}
#define U(x) __float_as_uint(x)
#define CP16(dst, src) \
    asm volatile("cp.async.cg.shared.global [%0], [%1], 16;" :: "r"(dst), "l"(src))
#define CP_COMMIT() asm volatile("cp.async.commit_group;" ::: "memory")
#define CP_WAIT1()  asm volatile("cp.async.wait_group 1;" ::: "memory")
#define CP_WAIT0()  asm volatile("cp.async.wait_group 0;" ::: "memory")
__device__ __forceinline__ uint32_t smem_u32(const void* p) {
    uint32_t a;
    asm("{ .reg .u64 t; cvta.to.shared.u64 t, %1; cvt.u32.u64 %0, t; }"
        : "=r"(a) : "l"(p));
    return a;
}

// ---------------------------------------------------------------------------
// Weight transpose
// ---------------------------------------------------------------------------
__global__ void transpose32(const float* __restrict__ src, float* __restrict__ dst,
                            int R, int C) {
    __shared__ float tb[32][33];
    int bx = blockIdx.x * 32, by = blockIdx.y * 32;
    int x = threadIdx.x, y = threadIdx.y;
    #pragma unroll
    for (int i = 0; i < 32; i += 8)
        tb[y + i][x] = src[(size_t)(by + y + i) * C + bx + x];
    __syncthreads();
    #pragma unroll
    for (int i = 0; i < 32; i += 8)
        dst[(size_t)(bx + y + i) * R + by + x] = tb[x][y + i];
}

// ---------------------------------------------------------------------------
// 3xTF32 mma.sync GEMM — exact R3/R4 version (known-good, 645us combined)
// ---------------------------------------------------------------------------
#define TSTR   36
#define TILE_F (128*TSTR)
#define GSMEM  (4*TILE_F*(int)sizeof(float))

__global__ __launch_bounds__(256) void tf32_gemm(
    const float* __restrict__ A,
    const float* __restrict__ Bt,
    const float* __restrict__ bias,
    float* __restrict__ outp, int mode)
{
    extern __shared__ float smf[];
    const int t   = threadIdx.x;
    const int wid = t >> 5, lane = t & 31;
    const int qr  = lane >> 2, qc = lane & 3;
    const int m0  = blockIdx.y * 128, n0 = blockIdx.x * 128;
    const int wm  = (wid & 3) * 32;
    const int wn  = (wid >> 2) * 64;

    const uint32_t sbase = smem_u32(smf);
    const int ldrow = t >> 3;
    const int ldk4  = (t & 7) * 4;

    float acc[2][8][4];
    #pragma unroll
    for (int i = 0; i < 2; i++)
        #pragma unroll
        for (int j = 0; j < 8; j++)
            #pragma unroll
            for (int e = 0; e < 4; e++) acc[i][j][e] = 0.f;

    auto load_chunk = [&](int c, int buf) {
        const int k0 = c * KCHUNK;
        const uint32_t ab = sbase + (uint32_t)(buf * 2 * TILE_F) * 4;
        const uint32_t bb = ab + (uint32_t)TILE_F * 4;
        #pragma unroll
        for (int i = 0; i < 4; i++) {
            const int row = ldrow + i * 32;
            CP16(ab + (uint32_t)(row * TSTR + ldk4) * 4,
                 A  + (size_t)(m0 + row) * KDIM + k0 + ldk4);
            CP16(bb + (uint32_t)(row * TSTR + ldk4) * 4,
                 Bt + (size_t)(n0 + row) * KDIM + k0 + ldk4);
        }
    };

    load_chunk(0, 0);
    CP_COMMIT();

    for (int c = 0; c < NCHUNK; c++) {
        const int buf = c & 1;
        if (c + 1 < NCHUNK) {
            load_chunk(c + 1, buf ^ 1);
            CP_COMMIT();
            CP_WAIT1();
        } else {
            CP_WAIT0();
        }
        __syncthreads();

        const float* As = smf + buf * 2 * TILE_F;
        const float* Bs = As + TILE_F;

        #pragma unroll
        for (int ks = 0; ks < 4; ks++) {
            const int kk = ks * 8;
            uint32_t ah[2][4], al[2][4];
            #pragma unroll
            for (int tm = 0; tm < 2; tm++) {
                const int mr = wm + tm * 16 + qr;
                split_tf32(As[(mr    ) * TSTR + kk + qc    ], ah[tm][0], al[tm][0]);
                split_tf32(As[(mr + 8) * TSTR + kk + qc    ], ah[tm][1], al[tm][1]);
                split_tf32(As[(mr    ) * TSTR + kk + qc + 4], ah[tm][2], al[tm][2]);
                split_tf32(As[(mr + 8) * TSTR + kk + qc + 4], ah[tm][3], al[tm][3]);
            }
            uint32_t bh[8][2], bl[8][2];
            #pragma unroll
            for (int tn = 0; tn < 8; tn++) {
                const int nr = wn + tn * 8 + qr;
                split_tf32(Bs[nr * TSTR + kk + qc    ], bh[tn][0], bl[tn][0]);
                split_tf32(Bs[nr * TSTR + kk + qc + 4], bh[tn][1], bl[tn][1]);
            }
            #pragma unroll
            for (int tm = 0; tm < 2; tm++)
                #pragma unroll
                for (int tn = 0; tn < 8; tn++) {
                    float* d = acc[tm][tn];
                    mma_tf32(d, ah[tm][0], ah[tm][1], ah[tm][2], ah[tm][3],
                             bh[tn][0], bh[tn][1]);
                    mma_tf32(d, ah[tm][0], ah[tm][1], ah[tm][2], ah[tm][3],
                             bl[tn][0], bl[tn][1]);
                    mma_tf32(d, al[tm][0], al[tm][1], al[tm][2], al[tm][3],
                             bh[tn][0], bh[tn][1]);
                }
        }
        __syncthreads();
    }

    #pragma unroll
    for (int tm = 0; tm < 2; tm++) {
        const int r0 = m0 + wm + tm * 16 + qr;
        #pragma unroll
        for (int tn = 0; tn < 8; tn++) {
            const int col = n0 + wn + tn * 8 + qc * 2;
            const float bz0 = bias[col], bz1 = bias[col + 1];
            #pragma unroll
            for (int half = 0; half < 2; half++) {
                const int row = r0 + half * 8;
                const float v0 = acc[tm][tn][half * 2 + 0] + bz0;
                const float v1 = acc[tm][tn][half * 2 + 1] + bz1;
                if (mode == 0) {
                    const int bb = row >> 11, s = row & (SEQ - 1);
                    const int h = col / 192, r = col - h * 192;
                    const int part = r >> 6, dd = r & 63;
                    float* dst = (part == 0) ? g_q : (part == 1) ? g_k : g_v;
                    *(float2*)&dst[(((size_t)(bb * NH + h)) * SEQ + s) * HD + dd] =
                        make_float2(v0, v1);
                } else {
                    *(float2*)&outp[(size_t)row * DIM + col] = make_float2(v0, v1);
                }
            }
        }
    }
}

// ---------------------------------------------------------------------------
// prep_pack: one-shot conditioning of q/k/v for the flash kernel.
//  g_qp: per row, 32 float4 packs (hi(2c*q[d0]), lo, hi(2c*q[d0+4]), lo),
//        d0 = (slot>>2)*8 + (slot&3)
//  g_kq: same pack of k (unscaled)
//  g_vp: [bh][s'][32 float4] where s' = (s>>3)*4+(s&3);
//        float4 = (v[a][2j], v[a+4][2j], v[a][2j+1], v[a+4][2j+1]) tf32-rounded
//  g_ksq: log2e * |k|^2
// ---------------------------------------------------------------------------
#define PSTAGE 68
#define PREP_SMEM (3*64*PSTAGE*(int)sizeof(float))   // 52224

__global__ __launch_bounds__(256) void prep_pack() {
    extern __shared__ float ps[];
    float* Sq = ps;
    float* Sk = ps + 64*PSTAGE;
    float* Sv = ps + 2*64*PSTAGE;
    const int t = threadIdx.x;
    const int bh = blockIdx.y, s0 = blockIdx.x * 64;
    const size_t base = (size_t)bh * SEQ * HD;

    // stage q/k/v, compute ksq via half-warp shuffle
    #pragma unroll
    for (int i = 0; i < 4; i++) {
        const int li = t + i * 256;
        const int row = li >> 4, c4 = (li & 15) << 2;
        const float4 q = *(const float4*)(g_q + base + (size_t)(s0 + row) * HD + c4);
        *(float4*)&Sq[row * PSTAGE + c4] = q;
        const float4 k = *(const float4*)(g_k + base + (size_t)(s0 + row) * HD + c4);
        *(float4*)&Sk[row * PSTAGE + c4] = k;
        float ss = fmaf(k.x, k.x, fmaf(k.y, k.y, fmaf(k.z, k.z, k.w * k.w)));
        #pragma unroll
        for (int off = 1; off <= 8; off <<= 1)
            ss += __shfl_xor_sync(0xffffffffu, ss, off);
        if ((t & 15) == 0)
            g_ksq[(size_t)bh * SEQ + s0 + row] = LOG2E * ss;
        const float4 v = *(const float4*)(g_v + base + (size_t)(s0 + row) * HD + c4);
        *(float4*)&Sv[row * PSTAGE + c4] = v;
    }
    __syncthreads();

    const size_t ob = ((size_t)bh * SEQ + s0) * 32;
    #pragma unroll
    for (int i = 0; i < 8; i++) {
        const int li = t + i * 256;
        const int r = li >> 5, slot = li & 31;
        const int d0 = (slot >> 2) * 8 + (slot & 3);
        float h0, l0, h1, l1;
        split2(C2LE * Sq[r * PSTAGE + d0], h0, l0);
        split2(C2LE * Sq[r * PSTAGE + d0 + 4], h1, l1);
        ((float4*)g_qp)[ob + r * 32 + slot] = make_float4(h0, l0, h1, l1);
        split2(Sk[r * PSTAGE + d0], h0, l0);
        split2(Sk[r * PSTAGE + d0 + 4], h1, l1);
        ((float4*)g_kq)[ob + r * 32 + slot] = make_float4(h0, l0, h1, l1);
    }
    const size_t vb = ((size_t)bh * (SEQ / 2) + (s0 >> 1)) * 32;
    #pragma unroll
    for (int i = 0; i < 4; i++) {
        const int li = t + i * 256;
        const int r = li >> 5, slot4 = li & 31;
        const int a = (r >> 2) * 8 + (r & 3);
        const int d2 = slot4 * 2;
        ((float4*)g_vp)[vb + r * 32 + slot4] = make_float4(
            tf32f(Sv[a * PSTAGE + d2]),       tf32f(Sv[(a + 4) * PSTAGE + d2]),
            tf32f(Sv[a * PSTAGE + d2 + 1]),   tf32f(Sv[(a + 4) * PSTAGE + d2 + 1]));
    }
}

// ---------------------------------------------------------------------------
// Flash attention v3: pre-packed operands, no-max softmax (logits <= 0),
// ex2-based exp with log2e folded upstream, per-thread l partials.
// smem: Kq float4 [64][36] (9216 floats, aliased as Ps after S-loop),
//       Vp float2 [32][84] (5376 floats), ksq [64]. Total 58624 B.
// ---------------------------------------------------------------------------
#define KQ4S 36
#define VP2S 84
#define PSTR 68
#define KQ_F (64*KQ4S*4)          // 9216 floats
#define VP_F (32*VP2S*2)          // 5376 floats
#define FLASH_SMEM ((KQ_F + VP_F + 64)*(int)sizeof(float))

__global__ __launch_bounds__(128, 3) void flash_mma() {
    extern __shared__ float s[];
    float4* Kq4  = (float4*)s;
    float4* Vp4  = (float4*)(s + KQ_F);
    float2* Vp2  = (float2*)(s + KQ_F);
    float*  ksqs = s + KQ_F + VP_F;
    float*  Ps   = s;                    // alias Kq after S-loop

    const int t = threadIdx.x, lane = t & 31, w = t >> 5;
    const int qr = lane >> 2, qc = lane & 3;
    const int wm = w * 16;
    const int bh = blockIdx.y;
    const int s0 = blockIdx.x * 64;
    const size_t rbase = (size_t)bh * SEQ;

    // Q fragments from g_qp (pre-scaled 2*log2e, pre-split)
    uint32_t qah[8][4], qal[8][4];
    {
        const float4* qp = (const float4*)g_qp;
        const size_t r0 = (rbase + s0 + wm + qr) * 32;
        const size_t r1 = r0 + 8 * 32;
        #pragma unroll
        for (int ks = 0; ks < 8; ks++) {
            const float4 f0 = qp[r0 + ks * 4 + qc];
            const float4 f1 = qp[r1 + ks * 4 + qc];
            qah[ks][0] = U(f0.x); qah[ks][1] = U(f1.x);
            qah[ks][2] = U(f0.z); qah[ks][3] = U(f1.z);
            qal[ks][0] = U(f0.y); qal[ks][1] = U(f1.y);
            qal[ks][2] = U(f0.w); qal[ks][3] = U(f1.w);
        }
    }

    float oacc[8][4];
    #pragma unroll
    for (int tn = 0; tn < 8; tn++)
        #pragma unroll
        for (int e = 0; e < 4; e++) oacc[tn][e] = 0.f;
    float l0r = 0.f, l1r = 0.f;

    for (int t0 = 0; t0 < SEQ; t0 += 64) {
        __syncthreads();   // prior-iter consumers of Ps(Kq)/Vp done
        // Load packed K tile (16 x LDG.128 -> STS.128)
        {
            const float4* kg = (const float4*)g_kq + (rbase + t0) * 32;
            #pragma unroll
            for (int i = 0; i < 16; i++) {
                const int li = t + i * 128;
                const int slot = li & 31, row = li >> 5;
                Kq4[row * KQ4S + slot] = kg[row * 32 + slot];
            }
        }
        // Load paired V tile (8 x LDG.128 -> STS.128)
        {
            const float4* vg = (const float4*)g_vp +
                               ((size_t)bh * (SEQ / 2) + (t0 >> 1)) * 32;
            #pragma unroll
            for (int i = 0; i < 8; i++) {
                const int li = t + i * 128;
                const int slot = li & 31, row = li >> 5;
                Vp4[row * (VP2S / 2) + slot] = vg[row * 32 + slot];
            }
        }
        if (t < 64) ksqs[t] = g_ksq[rbase + t0 + t];
        __syncthreads();

        // S = (2c*Q).K^T (3xTF32)
        float sacc[8][4];
        #pragma unroll
        for (int tn = 0; tn < 8; tn++)
            #pragma unroll
            for (int e = 0; e < 4; e++) sacc[tn][e] = 0.f;

        #pragma unroll
        for (int ks = 0; ks < 8; ks++) {
            #pragma unroll
            for (int tn = 0; tn < 8; tn++) {
                const float4 kk = Kq4[(tn * 8 + qr) * KQ4S + ks * 4 + qc];
                float* d = sacc[tn];
                mma_tf32(d, qah[ks][0], qah[ks][1], qah[ks][2], qah[ks][3],
                         U(kk.x), U(kk.z));
                mma_tf32(d, qah[ks][0], qah[ks][1], qah[ks][2], qah[ks][3],
                         U(kk.y), U(kk.w));
                mma_tf32(d, qal[ks][0], qal[ks][1], qal[ks][2], qal[ks][3],
                         U(kk.x), U(kk.z));
            }
        }
        __syncthreads();   // Kq dead -> alias as Ps

        // p = ex2(sacc - log2e*k^2); e^{-c q^2} factor cancels in the ratio.
        const float2* ksq2 = (const float2*)ksqs;
        #pragma unroll
        for (int tn = 0; tn < 8; tn++) {
            const float2 kk = ksq2[tn * 4 + qc];
            const float p0 = tf32f(ex2f(sacc[tn][0] - kk.x));
            const float p1 = tf32f(ex2f(sacc[tn][1] - kk.y));
            const float p2 = tf32f(ex2f(sacc[tn][2] - kk.x));
            const float p3 = tf32f(ex2f(sacc[tn][3] - kk.y));
            l0r += p0 + p1;
            l1r += p2 + p3;
            *(float2*)&Ps[(wm + qr    ) * PSTR + tn * 8 + 2 * qc] = make_float2(p0, p1);
            *(float2*)&Ps[(wm + qr + 8) * PSTR + tn * 8 + 2 * qc] = make_float2(p2, p3);
        }
        __syncwarp();   // Ps rows warp-private: order STS before LDS

        // O += P.V (1xTF32; paired V: one LDS.64 per b-frag)
        #pragma unroll
        for (int ks = 0; ks < 8; ks++) {
            const float* pp = Ps + (wm + qr) * PSTR + ks * 8 + qc;
            const uint32_t a0 = U(pp[0]);
            const uint32_t a1 = U(pp[8 * PSTR]);
            const uint32_t a2 = U(pp[4]);
            const uint32_t a3 = U(pp[8 * PSTR + 4]);
            #pragma unroll
            for (int tn = 0; tn < 8; tn++) {
                const float2 vv = Vp2[(ks * 4 + qc) * VP2S + tn * 8 + qr];
                mma_tf32(oacc[tn], a0, a1, a2, a3, U(vv.x), U(vv.y));
            }
        }
    }

    // Reduce l over the 4 qc lanes sharing each row, normalize, store.
    #pragma unroll
    for (int off = 1; off <= 2; off <<= 1) {
        l0r += __shfl_xor_sync(0xffffffffu, l0r, off);
        l1r += __shfl_xor_sync(0xffffffffu, l1r, off);
    }
    const float inv0 = 1.f / l0r, inv1 = 1.f / l1r;
    const int b = bh >> 4, h = bh & 15;
    const int row0 = s0 + wm + qr, row1 = row0 + 8;
    #pragma unroll
    for (int tn = 0; tn < 8; tn++) {
        const int col = h * HD + tn * 8 + 2 * qc;
        *(float2*)&g_att[(size_t)(b * SEQ + row0) * DIM + col] =
            make_float2(oacc[tn][0] * inv0, oacc[tn][1] * inv0);
        *(float2*)&g_att[(size_t)(b * SEQ + row1) * DIM + col] =
            make_float2(oacc[tn][2] * inv1, oacc[tn][3] * inv1);
    }
}

// ---------------------------------------------------------------------------
extern "C" void kernel_launch(void* const* d_in, const int* in_sizes, int n_in,
                              void* d_out, int out_size) {
    (void)in_sizes; (void)n_in; (void)out_size;
    const float* x    = (const float*)d_in[0];
    const float* Wqkv = (const float*)d_in[1];
    const float* bqkv = (const float*)d_in[2];
    const float* Wo   = (const float*)d_in[3];
    const float* bo   = (const float*)d_in[4];
    float*       out  = (float*)d_out;

    float* wqt; cudaGetSymbolAddress((void**)&wqt, g_wqt);
    float* wot; cudaGetSymbolAddress((void**)&wot, g_wot);
    float* att; cudaGetSymbolAddress((void**)&att, g_att);

    cudaFuncSetAttribute(tf32_gemm, cudaFuncAttributeMaxDynamicSharedMemorySize, GSMEM);
    cudaFuncSetAttribute(prep_pack, cudaFuncAttributeMaxDynamicSharedMemorySize, PREP_SMEM);
    cudaFuncSetAttribute(flash_mma, cudaFuncAttributeMaxDynamicSharedMemorySize, FLASH_SMEM);

    transpose32<<<dim3(N_QKV/32, KDIM/32), dim3(32, 8)>>>(Wqkv, wqt, KDIM, N_QKV);
    transpose32<<<dim3(DIM/32,  KDIM/32), dim3(32, 8)>>>(Wo,   wot, KDIM, DIM);

    tf32_gemm<<<dim3(N_QKV/128, M_ROWS/128), 256, GSMEM>>>(x, wqt, bqkv, nullptr, 0);

    prep_pack<<<dim3(SEQ/64, NUM_B*NH), 256, PREP_SMEM>>>();

    flash_mma<<<dim3(SEQ/64, NUM_B*NH), 128, FLASH_SMEM>>>();

    tf32_gemm<<<dim3(DIM/128, M_ROWS/128), 256, GSMEM>>>(att, wot, bo, out, 1);
}

// round 7
// speedup vs baseline: 1.5248x; 1.3436x over previous
#include <cuda_runtime.h>
#include <cuda_bf16.h>
#include <cstdint>

#define NUM_B 2
#define SEQ   2048
#define DIM   1024
#define NH    16
#define HD    64
#define M_ROWS (NUM_B*SEQ)
#define N_QKV  (3*DIM)
#define KDIM   DIM
#define KCHUNK 32
#define NCHUNK (KDIM/KCHUNK)

#define LOG2E 1.4426950408889634f
#define C2LE  2.8853900817779268f   // 2*log2(e)

// Scratch
__device__ float g_q  [(size_t)NUM_B*NH*SEQ*HD];
__device__ float g_k  [(size_t)NUM_B*NH*SEQ*HD];
__device__ float g_v  [(size_t)NUM_B*NH*SEQ*HD];
__device__ float g_att[(size_t)M_ROWS*DIM];
__device__ float g_wqt[(size_t)N_QKV*KDIM];
__device__ float g_wot[(size_t)DIM*KDIM];
// Packed flash operands (one-shot by prep_pack)
__device__ uint4 g_qpb[(size_t)NUM_B*NH*SEQ*16];     // 2c*q bf16 hi/lo frag-packed
__device__ uint4 g_kqb[(size_t)NUM_B*NH*SEQ*16];     // k bf16 hi/lo frag-packed
__device__ float g_vp [(size_t)NUM_B*NH*(SEQ/2)*2*HD]; // v tf32, key-paired
__device__ float g_ksq[(size_t)NUM_B*NH*SEQ];        // log2e*|k|^2

// ---------------------------------------------------------------------------
// Helpers
// ---------------------------------------------------------------------------
__device__ __forceinline__ float tf32f(float x) {
    float r;
    asm("cvt.rna.tf32.f32 %0, %1;" : "=f"(r) : "f"(x));
    return r;
}
__device__ __forceinline__ float ex2f(float x) {
    float r;
    asm("ex2.approx.f32 %0, %1;" : "=f"(r) : "f"(x));
    return r;
}
__device__ __forceinline__ void split2(float x, float& h, float& l) {
    asm("cvt.rna.tf32.f32 %0, %1;" : "=f"(h) : "f"(x));
    float r = x - h;
    asm("cvt.rna.tf32.f32 %0, %1;" : "=f"(l) : "f"(r));
}
__device__ __forceinline__ void split_tf32(float x, uint32_t& hi, uint32_t& lo) {
    float h, l;
    split2(x, h, l);
    hi = __float_as_uint(h);
    lo = __float_as_uint(l);
}
__device__ __forceinline__ void bsplit(float x, float& h, float& l) {
    h = __bfloat162float(__float2bfloat16_rn(x));
    l = x - h;
}
__device__ __forceinline__ uint32_t bpack(float a, float b) {
    __nv_bfloat162 t = __floats2bfloat162_rn(a, b);
    return *(uint32_t*)&t;
}
__device__ __forceinline__ void mma_tf32(float* d,
                                         uint32_t a0, uint32_t a1, uint32_t a2, uint32_t a3,
                                         uint32_t b0, uint32_t b1) {
    asm volatile(
        "mma.sync.aligned.m16n8k8.row.col.f32.tf32.tf32.f32 "
        "{%0,%1,%2,%3}, {%4,%5,%6,%7}, {%8,%9}, {%0,%1,%2,%3};"
        : "+f"(d[0]), "+f"(d[1]), "+f"(d[2]), "+f"(d[3])
        : "r"(a0), "r"(a1), "r"(a2), "r"(a3), "r"(b0), "r"(b1));
}
__device__ __forceinline__ void mma_bf16(float* d,
                                         uint32_t a0, uint32_t a1, uint32_t a2, uint32_t a3,
                                         uint32_t b0, uint32_t b1) {
    asm volatile(
        "mma.sync.aligned.m16n8k16.row.col.f32.bf16.bf16.f32 "
        "{%0,%1,%2,%3}, {%4,%5,%6,%7}, {%8,%9}, {%0,%1,%2,%3};"
        : "+f"(d[0]), "+f"(d[1]), "+f"(d[2]), "+f"(d[3])
        : "r"(a0), "r"(a1), "r"(a2), "r"(a3), "r"(b0), "r"(b1));
}
#define U(x) __float_as_uint(x)
#define CP16(dst, src) \
    asm volatile("cp.async.cg.shared.global [%0], [%1], 16;" :: "r"(dst), "l"(src))
#define CP_COMMIT() asm volatile("cp.async.commit_group;" ::: "memory")
#define CP_WAIT1()  asm volatile("cp.async.wait_group 1;" ::: "memory")
#define CP_WAIT0()  asm volatile("cp.async.wait_group 0;" ::: "memory")
__device__ __forceinline__ uint32_t smem_u32(const void* p) {
    uint32_t a;
    asm("{ .reg .u64 t; cvta.to.shared.u64 t, %1; cvt.u32.u64 %0, t; }"
        : "=r"(a) : "l"(p));
    return a;
}

// ---------------------------------------------------------------------------
// Weight transpose
// ---------------------------------------------------------------------------
__global__ void transpose32(const float* __restrict__ src, float* __restrict__ dst,
                            int R, int C) {
    __shared__ float tb[32][33];
    int bx = blockIdx.x * 32, by = blockIdx.y * 32;
    int x = threadIdx.x, y = threadIdx.y;
    #pragma unroll
    for (int i = 0; i < 32; i += 8)
        tb[y + i][x] = src[(size_t)(by + y + i) * C + bx + x];
    __syncthreads();
    #pragma unroll
    for (int i = 0; i < 32; i += 8)
        dst[(size_t)(bx + y + i) * R + by + x] = tb[x][y + i];
}

// ---------------------------------------------------------------------------
// 3xTF32 mma.sync GEMM — known-good R3/R4 version
// ---------------------------------------------------------------------------
#define TSTR   36
#define TILE_F (128*TSTR)
#define GSMEM  (4*TILE_F*(int)sizeof(float))

__global__ __launch_bounds__(256) void tf32_gemm(
    const float* __restrict__ A,
    const float* __restrict__ Bt,
    const float* __restrict__ bias,
    float* __restrict__ outp, int mode)
{
    extern __shared__ float smf[];
    const int t   = threadIdx.x;
    const int wid = t >> 5, lane = t & 31;
    const int qr  = lane >> 2, qc = lane & 3;
    const int m0  = blockIdx.y * 128, n0 = blockIdx.x * 128;
    const int wm  = (wid & 3) * 32;
    const int wn  = (wid >> 2) * 64;

    const uint32_t sbase = smem_u32(smf);
    const int ldrow = t >> 3;
    const int ldk4  = (t & 7) * 4;

    float acc[2][8][4];
    #pragma unroll
    for (int i = 0; i < 2; i++)
        #pragma unroll
        for (int j = 0; j < 8; j++)
            #pragma unroll
            for (int e = 0; e < 4; e++) acc[i][j][e] = 0.f;

    auto load_chunk = [&](int c, int buf) {
        const int k0 = c * KCHUNK;
        const uint32_t ab = sbase + (uint32_t)(buf * 2 * TILE_F) * 4;
        const uint32_t bb = ab + (uint32_t)TILE_F * 4;
        #pragma unroll
        for (int i = 0; i < 4; i++) {
            const int row = ldrow + i * 32;
            CP16(ab + (uint32_t)(row * TSTR + ldk4) * 4,
                 A  + (size_t)(m0 + row) * KDIM + k0 + ldk4);
            CP16(bb + (uint32_t)(row * TSTR + ldk4) * 4,
                 Bt + (size_t)(n0 + row) * KDIM + k0 + ldk4);
        }
    };

    load_chunk(0, 0);
    CP_COMMIT();

    for (int c = 0; c < NCHUNK; c++) {
        const int buf = c & 1;
        if (c + 1 < NCHUNK) {
            load_chunk(c + 1, buf ^ 1);
            CP_COMMIT();
            CP_WAIT1();
        } else {
            CP_WAIT0();
        }
        __syncthreads();

        const float* As = smf + buf * 2 * TILE_F;
        const float* Bs = As + TILE_F;

        #pragma unroll
        for (int ks = 0; ks < 4; ks++) {
            const int kk = ks * 8;
            uint32_t ah[2][4], al[2][4];
            #pragma unroll
            for (int tm = 0; tm < 2; tm++) {
                const int mr = wm + tm * 16 + qr;
                split_tf32(As[(mr    ) * TSTR + kk + qc    ], ah[tm][0], al[tm][0]);
                split_tf32(As[(mr + 8) * TSTR + kk + qc    ], ah[tm][1], al[tm][1]);
                split_tf32(As[(mr    ) * TSTR + kk + qc + 4], ah[tm][2], al[tm][2]);
                split_tf32(As[(mr + 8) * TSTR + kk + qc + 4], ah[tm][3], al[tm][3]);
            }
            uint32_t bh[8][2], bl[8][2];
            #pragma unroll
            for (int tn = 0; tn < 8; tn++) {
                const int nr = wn + tn * 8 + qr;
                split_tf32(Bs[nr * TSTR + kk + qc    ], bh[tn][0], bl[tn][0]);
                split_tf32(Bs[nr * TSTR + kk + qc + 4], bh[tn][1], bl[tn][1]);
            }
            #pragma unroll
            for (int tm = 0; tm < 2; tm++)
                #pragma unroll
                for (int tn = 0; tn < 8; tn++) {
                    float* d = acc[tm][tn];
                    mma_tf32(d, ah[tm][0], ah[tm][1], ah[tm][2], ah[tm][3],
                             bh[tn][0], bh[tn][1]);
                    mma_tf32(d, ah[tm][0], ah[tm][1], ah[tm][2], ah[tm][3],
                             bl[tn][0], bl[tn][1]);
                    mma_tf32(d, al[tm][0], al[tm][1], al[tm][2], al[tm][3],
                             bh[tn][0], bh[tn][1]);
                }
        }
        __syncthreads();
    }

    #pragma unroll
    for (int tm = 0; tm < 2; tm++) {
        const int r0 = m0 + wm + tm * 16 + qr;
        #pragma unroll
        for (int tn = 0; tn < 8; tn++) {
            const int col = n0 + wn + tn * 8 + qc * 2;
            const float bz0 = bias[col], bz1 = bias[col + 1];
            #pragma unroll
            for (int half = 0; half < 2; half++) {
                const int row = r0 + half * 8;
                const float v0 = acc[tm][tn][half * 2 + 0] + bz0;
                const float v1 = acc[tm][tn][half * 2 + 1] + bz1;
                if (mode == 0) {
                    const int bb = row >> 11, s = row & (SEQ - 1);
                    const int h = col / 192, r = col - h * 192;
                    const int part = r >> 6, dd = r & 63;
                    float* dst = (part == 0) ? g_q : (part == 1) ? g_k : g_v;
                    *(float2*)&dst[(((size_t)(bb * NH + h)) * SEQ + s) * HD + dd] =
                        make_float2(v0, v1);
                } else {
                    *(float2*)&outp[(size_t)row * DIM + col] = make_float2(v0, v1);
                }
            }
        }
    }
}

// ---------------------------------------------------------------------------
// prep_pack v2: bf16 hi/lo fragment packing for QK^T, tf32 paired V, ksq.
//  g_qpb/g_kqb per row: 16 uint4 slots; slot = ks*4 + qc3:
//    cols c0 = ks*16 + 2*qc3 (+1), c8 = c0+8 (+1)
//    uint4 = ( bf16x2(h(c0),h(c0+1)), bf16x2(h(c8),h(c8+1)),
//              bf16x2(l(c0),l(c0+1)), bf16x2(l(c8),l(c8+1)) )
// ---------------------------------------------------------------------------
#define PSTAGE 68
#define PREP_SMEM (3*64*PSTAGE*(int)sizeof(float))

__global__ __launch_bounds__(256) void prep_pack() {
    extern __shared__ float ps[];
    float* Sq = ps;
    float* Sk = ps + 64*PSTAGE;
    float* Sv = ps + 2*64*PSTAGE;
    const int t = threadIdx.x;
    const int bh = blockIdx.y, s0 = blockIdx.x * 64;
    const size_t base = (size_t)bh * SEQ * HD;

    #pragma unroll
    for (int i = 0; i < 4; i++) {
        const int li = t + i * 256;
        const int row = li >> 4, c4 = (li & 15) << 2;
        const float4 q = *(const float4*)(g_q + base + (size_t)(s0 + row) * HD + c4);
        *(float4*)&Sq[row * PSTAGE + c4] = q;
        const float4 k = *(const float4*)(g_k + base + (size_t)(s0 + row) * HD + c4);
        *(float4*)&Sk[row * PSTAGE + c4] = k;
        float ss = fmaf(k.x, k.x, fmaf(k.y, k.y, fmaf(k.z, k.z, k.w * k.w)));
        #pragma unroll
        for (int off = 1; off <= 8; off <<= 1)
            ss += __shfl_xor_sync(0xffffffffu, ss, off);
        if ((t & 15) == 0)
            g_ksq[(size_t)bh * SEQ + s0 + row] = LOG2E * ss;
        const float4 v = *(const float4*)(g_v + base + (size_t)(s0 + row) * HD + c4);
        *(float4*)&Sv[row * PSTAGE + c4] = v;
    }
    __syncthreads();

    const size_t ob = ((size_t)bh * SEQ + s0) * 16;
    #pragma unroll
    for (int i = 0; i < 4; i++) {
        const int li = t + i * 256;             // 0..1023
        const int r = li >> 4, slot = li & 15;
        const int ks = slot >> 2, q3 = slot & 3;
        const int c0 = ks * 16 + 2 * q3, c8 = c0 + 8;
        float h0, l0, h1, l1, h2, l2, h3, l3;
        // Q (pre-scaled by 2*log2e)
        bsplit(C2LE * Sq[r * PSTAGE + c0    ], h0, l0);
        bsplit(C2LE * Sq[r * PSTAGE + c0 + 1], h1, l1);
        bsplit(C2LE * Sq[r * PSTAGE + c8    ], h2, l2);
        bsplit(C2LE * Sq[r * PSTAGE + c8 + 1], h3, l3);
        g_qpb[ob + r * 16 + slot] =
            make_uint4(bpack(h0, h1), bpack(h2, h3), bpack(l0, l1), bpack(l2, l3));
        // K
        bsplit(Sk[r * PSTAGE + c0    ], h0, l0);
        bsplit(Sk[r * PSTAGE + c0 + 1], h1, l1);
        bsplit(Sk[r * PSTAGE + c8    ], h2, l2);
        bsplit(Sk[r * PSTAGE + c8 + 1], h3, l3);
        g_kqb[ob + r * 16 + slot] =
            make_uint4(bpack(h0, h1), bpack(h2, h3), bpack(l0, l1), bpack(l2, l3));
    }
    // V: paired tf32 (unchanged from R6)
    const size_t vb = ((size_t)bh * (SEQ / 2) + (s0 >> 1)) * 32;
    #pragma unroll
    for (int i = 0; i < 4; i++) {
        const int li = t + i * 256;
        const int r = li >> 5, slot4 = li & 31;
        const int a = (r >> 2) * 8 + (r & 3);
        const int d2 = slot4 * 2;
        ((float4*)g_vp)[vb + r * 32 + slot4] = make_float4(
            tf32f(Sv[a * PSTAGE + d2]),     tf32f(Sv[(a + 4) * PSTAGE + d2]),
            tf32f(Sv[a * PSTAGE + d2 + 1]), tf32f(Sv[(a + 4) * PSTAGE + d2 + 1]));
    }
}

// ---------------------------------------------------------------------------
// Flash attention v4: QK^T in 3xBF16 m16n8k16 (half the tensor cycles of
// 3xTF32 k8), PV in 1xTF32. No-max softmax (logits <= 0), ex2 exp.
// smem: Kb4 uint4[64][20] (20480B, aliased as Ps), Vp (21504B), ksq (256B).
// ---------------------------------------------------------------------------
#define KB4S 20                   // uint4 stride per key (16 + 4 pad)
#define KB_W (64*KB4S*4)          // 5120 floats
#define VP2S 84
#define VP_F (32*VP2S*2)          // 5376 floats
#define PSTR 68
#define FLASH_SMEM ((KB_W + VP_F + 64)*(int)sizeof(float))   // 42240 B

__global__ __launch_bounds__(128, 3) void flash_mma() {
    extern __shared__ float s[];
    uint4*  Kb4  = (uint4*)s;
    float4* Vp4  = (float4*)(s + KB_W);
    float2* Vp2  = (float2*)(s + KB_W);
    float*  ksqs = s + KB_W + VP_F;
    float*  Ps   = s;                    // alias Kb4 after S-loop

    const int t = threadIdx.x, lane = t & 31, w = t >> 5;
    const int qr = lane >> 2, qc = lane & 3;
    const int wm = w * 16;
    const int bh = blockIdx.y;
    const int s0 = blockIdx.x * 64;
    const size_t rbase = (size_t)bh * SEQ;

    // Q fragments (bf16 hi/lo) — loop-invariant
    uint32_t qh[4][4], ql[4][4];
    {
        const uint4* q0 = g_qpb + (rbase + s0 + wm + qr) * 16;
        const uint4* q1 = q0 + 8 * 16;
        #pragma unroll
        for (int ks = 0; ks < 4; ks++) {
            const uint4 f0 = q0[ks * 4 + qc];
            const uint4 f1 = q1[ks * 4 + qc];
            qh[ks][0] = f0.x; qh[ks][1] = f1.x; qh[ks][2] = f0.y; qh[ks][3] = f1.y;
            ql[ks][0] = f0.z; ql[ks][1] = f1.z; ql[ks][2] = f0.w; ql[ks][3] = f1.w;
        }
    }

    float oacc[8][4];
    #pragma unroll
    for (int tn = 0; tn < 8; tn++)
        #pragma unroll
        for (int e = 0; e < 4; e++) oacc[tn][e] = 0.f;
    float l0r = 0.f, l1r = 0.f;

    for (int t0 = 0; t0 < SEQ; t0 += 64) {
        __syncthreads();   // prior-iter consumers of Ps(Kb4)/Vp done
        // K tile: 1024 uint4, 8 x LDG.128 -> STS.128 per thread
        {
            const uint4* kg = g_kqb + (rbase + t0) * 16;
            #pragma unroll
            for (int i = 0; i < 8; i++) {
                const int li = t + i * 128;
                const int row = li >> 4, slot = li & 15;
                Kb4[row * KB4S + slot] = kg[row * 16 + slot];
            }
        }
        // V tile: 8 x LDG.128 -> STS.128
        {
            const float4* vg = (const float4*)g_vp +
                               ((size_t)bh * (SEQ / 2) + (t0 >> 1)) * 32;
            #pragma unroll
            for (int i = 0; i < 8; i++) {
                const int li = t + i * 128;
                const int slot = li & 31, row = li >> 5;
                Vp4[row * (VP2S / 2) + slot] = vg[row * 32 + slot];
            }
        }
        if (t < 64) ksqs[t] = g_ksq[rbase + t0 + t];
        __syncthreads();

        // S = (2c*Q).K^T — 3xBF16, 4 k16-steps
        float sacc[8][4];
        #pragma unroll
        for (int tn = 0; tn < 8; tn++)
            #pragma unroll
            for (int e = 0; e < 4; e++) sacc[tn][e] = 0.f;

        #pragma unroll
        for (int ks = 0; ks < 4; ks++) {
            #pragma unroll
            for (int tn = 0; tn < 8; tn++) {
                const uint4 wv = Kb4[(tn * 8 + qr) * KB4S + ks * 4 + qc];
                float* d = sacc[tn];
                mma_bf16(d, qh[ks][0], qh[ks][1], qh[ks][2], qh[ks][3], wv.x, wv.y);
                mma_bf16(d, qh[ks][0], qh[ks][1], qh[ks][2], qh[ks][3], wv.z, wv.w);
                mma_bf16(d, ql[ks][0], ql[ks][1], ql[ks][2], ql[ks][3], wv.x, wv.y);
            }
        }
        __syncthreads();   // Kb4 dead -> alias as Ps

        // p = ex2(sacc - log2e*|k|^2)
        const float2* ksq2 = (const float2*)ksqs;
        #pragma unroll
        for (int tn = 0; tn < 8; tn++) {
            const float2 kk = ksq2[tn * 4 + qc];
            const float p0 = tf32f(ex2f(sacc[tn][0] - kk.x));
            const float p1 = tf32f(ex2f(sacc[tn][1] - kk.y));
            const float p2 = tf32f(ex2f(sacc[tn][2] - kk.x));
            const float p3 = tf32f(ex2f(sacc[tn][3] - kk.y));
            l0r += p0 + p1;
            l1r += p2 + p3;
            *(float2*)&Ps[(wm + qr    ) * PSTR + tn * 8 + 2 * qc] = make_float2(p0, p1);
            *(float2*)&Ps[(wm + qr + 8) * PSTR + tn * 8 + 2 * qc] = make_float2(p2, p3);
        }
        __syncwarp();   // Ps rows warp-private: order STS before LDS

        // O += P.V (1xTF32, paired V)
        #pragma unroll
        for (int ks = 0; ks < 8; ks++) {
            const float* pp = Ps + (wm + qr) * PSTR + ks * 8 + qc;
            const uint32_t a0 = U(pp[0]);
            const uint32_t a1 = U(pp[8 * PSTR]);
            const uint32_t a2 = U(pp[4]);
            const uint32_t a3 = U(pp[8 * PSTR + 4]);
            #pragma unroll
            for (int tn = 0; tn < 8; tn++) {
                const float2 vv = Vp2[(ks * 4 + qc) * VP2S + tn * 8 + qr];
                mma_tf32(oacc[tn], a0, a1, a2, a3, U(vv.x), U(vv.y));
            }
        }
    }

    #pragma unroll
    for (int off = 1; off <= 2; off <<= 1) {
        l0r += __shfl_xor_sync(0xffffffffu, l0r, off);
        l1r += __shfl_xor_sync(0xffffffffu, l1r, off);
    }
    const float inv0 = 1.f / l0r, inv1 = 1.f / l1r;
    const int b = bh >> 4, h = bh & 15;
    const int row0 = s0 + wm + qr, row1 = row0 + 8;
    #pragma unroll
    for (int tn = 0; tn < 8; tn++) {
        const int col = h * HD + tn * 8 + 2 * qc;
        *(float2*)&g_att[(size_t)(b * SEQ + row0) * DIM + col] =
            make_float2(oacc[tn][0] * inv0, oacc[tn][1] * inv0);
        *(float2*)&g_att[(size_t)(b * SEQ + row1) * DIM + col] =
            make_float2(oacc[tn][2] * inv1, oacc[tn][3] * inv1);
    }
}

// ---------------------------------------------------------------------------
extern "C" void kernel_launch(void* const* d_in, const int* in_sizes, int n_in,
                              void* d_out, int out_size) {
    (void)in_sizes; (void)n_in; (void)out_size;
    const float* x    = (const float*)d_in[0];
    const float* Wqkv = (const float*)d_in[1];
    const float* bqkv = (const float*)d_in[2];
    const float* Wo   = (const float*)d_in[3];
    const float* bo   = (const float*)d_in[4];
    float*       out  = (float*)d_out;

    float* wqt; cudaGetSymbolAddress((void**)&wqt, g_wqt);
    float* wot; cudaGetSymbolAddress((void**)&wot, g_wot);
    float* att; cudaGetSymbolAddress((void**)&att, g_att);

    cudaFuncSetAttribute(tf32_gemm, cudaFuncAttributeMaxDynamicSharedMemorySize, GSMEM);
    cudaFuncSetAttribute(prep_pack, cudaFuncAttributeMaxDynamicSharedMemorySize, PREP_SMEM);
    cudaFuncSetAttribute(flash_mma, cudaFuncAttributeMaxDynamicSharedMemorySize, FLASH_SMEM);

    transpose32<<<dim3(N_QKV/32, KDIM/32), dim3(32, 8)>>>(Wqkv, wqt, KDIM, N_QKV);
    transpose32<<<dim3(DIM/32,  KDIM/32), dim3(32, 8)>>>(Wo,   wot, KDIM, DIM);

    tf32_gemm<<<dim3(N_QKV/128, M_ROWS/128), 256, GSMEM>>>(x, wqt, bqkv, nullptr, 0);

    prep_pack<<<dim3(SEQ/64, NUM_B*NH), 256, PREP_SMEM>>>();

    flash_mma<<<dim3(SEQ/64, NUM_B*NH), 128, FLASH_SMEM>>>();

    tf32_gemm<<<dim3(DIM/128, M_ROWS/128), 256, GSMEM>>>(att, wot, bo, out, 1);
}

// round 8
// speedup vs baseline: 2.2495x; 1.4753x over previous
#include <cuda_runtime.h>
#include <cuda_bf16.h>
#include <cstdint>

#define NUM_B 2
#define SEQ   2048
#define DIM   1024
#define NH    16
#define HD    64
#define M_ROWS (NUM_B*SEQ)
#define N_QKV  (3*DIM)
#define KDIM   DIM
#define NCH    (KDIM/32)          // 32 K-chunks of 32

#define LOG2E 1.4426950408889634f
#define C2LE  2.8853900817779268f

// Scratch
__device__ float g_q  [(size_t)NUM_B*NH*SEQ*HD];
__device__ float g_k  [(size_t)NUM_B*NH*SEQ*HD];
__device__ float g_v  [(size_t)NUM_B*NH*SEQ*HD];
// bf16 hi/lo fragment-packed operands (uint4 = (h01,h89,l01,l89) per 4 cols)
__device__ uint4 g_xp  [(size_t)M_ROWS*256];    // x packed          [mblk][c][s][r]
__device__ uint4 g_attp[(size_t)M_ROWS*256];    // attention output packed
__device__ uint4 g_wqp [(size_t)N_QKV*256];     // W_qkv^T packed    [nblk][c][s][r]
__device__ uint4 g_wop [(size_t)DIM*256];       // W_o^T packed
// flash operands (unchanged from R7)
__device__ uint4 g_qpb[(size_t)NUM_B*NH*SEQ*16];
__device__ uint4 g_kqb[(size_t)NUM_B*NH*SEQ*16];
__device__ float g_vp [(size_t)NUM_B*NH*(SEQ/2)*2*HD];
__device__ float g_ksq[(size_t)NUM_B*NH*SEQ];

// ---------------------------------------------------------------------------
// Helpers
// ---------------------------------------------------------------------------
__device__ __forceinline__ float tf32f(float x) {
    float r;
    asm("cvt.rna.tf32.f32 %0, %1;" : "=f"(r) : "f"(x));
    return r;
}
__device__ __forceinline__ float ex2f(float x) {
    float r;
    asm("ex2.approx.f32 %0, %1;" : "=f"(r) : "f"(x));
    return r;
}
__device__ __forceinline__ void bsplit(float x, float& h, float& l) {
    h = __bfloat162float(__float2bfloat16_rn(x));
    l = x - h;
}
__device__ __forceinline__ uint32_t bpack(float a, float b) {
    __nv_bfloat162 t = __floats2bfloat162_rn(a, b);
    return *(uint32_t*)&t;
}
__device__ __forceinline__ void mma_tf32(float* d,
                                         uint32_t a0, uint32_t a1, uint32_t a2, uint32_t a3,
                                         uint32_t b0, uint32_t b1) {
    asm volatile(
        "mma.sync.aligned.m16n8k8.row.col.f32.tf32.tf32.f32 "
        "{%0,%1,%2,%3}, {%4,%5,%6,%7}, {%8,%9}, {%0,%1,%2,%3};"
        : "+f"(d[0]), "+f"(d[1]), "+f"(d[2]), "+f"(d[3])
        : "r"(a0), "r"(a1), "r"(a2), "r"(a3), "r"(b0), "r"(b1));
}
__device__ __forceinline__ void mma_bf16(float* d,
                                         uint32_t a0, uint32_t a1, uint32_t a2, uint32_t a3,
                                         uint32_t b0, uint32_t b1) {
    asm volatile(
        "mma.sync.aligned.m16n8k16.row.col.f32.bf16.bf16.f32 "
        "{%0,%1,%2,%3}, {%4,%5,%6,%7}, {%8,%9}, {%0,%1,%2,%3};"
        : "+f"(d[0]), "+f"(d[1]), "+f"(d[2]), "+f"(d[3])
        : "r"(a0), "r"(a1), "r"(a2), "r"(a3), "r"(b0), "r"(b1));
}
#define U(x) __float_as_uint(x)
#define CP16(dst, src) \
    asm volatile("cp.async.cg.shared.global [%0], [%1], 16;" :: "r"(dst), "l"(src))
#define CP_COMMIT() asm volatile("cp.async.commit_group;" ::: "memory")
#define CP_WAIT1()  asm volatile("cp.async.wait_group 1;" ::: "memory")
#define CP_WAIT0()  asm volatile("cp.async.wait_group 0;" ::: "memory")
__device__ __forceinline__ uint32_t smem_u32(const void* p) {
    uint32_t a;
    asm("{ .reg .u64 t; cvta.to.shared.u64 t, %1; cvt.u32.u64 %0, t; }"
        : "=r"(a) : "l"(p));
    return a;
}

// ---------------------------------------------------------------------------
// pack_w: W [KDIM][N] -> packed [nblk][c][s][r]  (B operand / K-major rows)
// ---------------------------------------------------------------------------
__global__ __launch_bounds__(256) void pack_w(const float* __restrict__ W,
                                              uint4* __restrict__ outp, int N) {
    __shared__ float Sw[32 * 136];
    const int t = threadIdx.x;
    const int n0 = blockIdx.x * 128, k0 = blockIdx.y * 32;
    #pragma unroll
    for (int i = 0; i < 4; i++) {
        const int idx = t + i * 256;
        const int kr = idx >> 5, c4 = (idx & 31) * 4;
        *(float4*)&Sw[kr * 136 + c4] =
            *(const float4*)(W + (size_t)(k0 + kr) * N + n0 + c4);
    }
    __syncthreads();
    const size_t ob = ((size_t)blockIdx.x * NCH + blockIdx.y) * 8 * 128;
    #pragma unroll
    for (int i = 0; i < 4; i++) {
        const int idx = t + i * 256;
        const int s = idx >> 7, r = idx & 127;
        const int c0 = (s >> 2) * 16 + 2 * (s & 3), c8 = c0 + 8;
        float h0, l0, h1, l1, h2, l2, h3, l3;
        bsplit(Sw[(c0    ) * 136 + r], h0, l0);
        bsplit(Sw[(c0 + 1) * 136 + r], h1, l1);
        bsplit(Sw[(c8    ) * 136 + r], h2, l2);
        bsplit(Sw[(c8 + 1) * 136 + r], h3, l3);
        outp[ob + s * 128 + r] =
            make_uint4(bpack(h0, h1), bpack(h2, h3), bpack(l0, l1), bpack(l2, l3));
    }
}

// ---------------------------------------------------------------------------
// pack_x: A [M][K] row-major -> packed [mblk][c][s][r]
// ---------------------------------------------------------------------------
__global__ __launch_bounds__(256) void pack_x(const float* __restrict__ A,
                                              uint4* __restrict__ outp) {
    __shared__ float Sx[128 * 36];
    const int t = threadIdx.x;
    const int m0 = blockIdx.x * 128, k0 = blockIdx.y * 32;
    #pragma unroll
    for (int i = 0; i < 4; i++) {
        const int idx = t + i * 256;
        const int row = idx >> 3, c4 = (idx & 7) * 4;
        *(float4*)&Sx[row * 36 + c4] =
            *(const float4*)(A + (size_t)(m0 + row) * KDIM + k0 + c4);
    }
    __syncthreads();
    const size_t ob = ((size_t)blockIdx.x * NCH + blockIdx.y) * 8 * 128;
    #pragma unroll
    for (int i = 0; i < 4; i++) {
        const int idx = t + i * 256;
        const int s = idx >> 7, r = idx & 127;
        const int c0 = (s >> 2) * 16 + 2 * (s & 3), c8 = c0 + 8;
        float h0, l0, h1, l1, h2, l2, h3, l3;
        bsplit(Sx[r * 36 + c0    ], h0, l0);
        bsplit(Sx[r * 36 + c0 + 1], h1, l1);
        bsplit(Sx[r * 36 + c8    ], h2, l2);
        bsplit(Sx[r * 36 + c8 + 1], h3, l3);
        outp[ob + s * 128 + r] =
            make_uint4(bpack(h0, h1), bpack(h2, h3), bpack(l0, l1), bpack(l2, l3));
    }
}

// ---------------------------------------------------------------------------
// 3xBF16 GEMM: C[m,n] = A[m,:].Bt[n,:] + bias[n]; operands pre-packed.
// 128x128 tile, K-chunk 32 (2 k16 steps), double-buffered cp.async.
// Hot loop: 24 LDS.128 + 96 HMMA per warp-chunk. Bank-clean (stride 130 uint4).
// ---------------------------------------------------------------------------
#define BRS    130
#define BSTAGE (8*BRS)                        // 1040 uint4 per operand stage
#define GSMEM2 (2*2*BSTAGE*16)                // 66560 B

__global__ __launch_bounds__(256) void bf16_gemm(
    const uint4* __restrict__ Ap,
    const uint4* __restrict__ Bp,
    const float* __restrict__ bias,
    float* __restrict__ outp, int mode)
{
    extern __shared__ uint4 sm4[];
    const uint32_t sbase = smem_u32(sm4);
    const int t = threadIdx.x, wid = t >> 5, lane = t & 31;
    const int qr = lane >> 2, qc = lane & 3;
    const int m0 = blockIdx.y * 128, n0 = blockIdx.x * 128;
    const int wm = (wid & 3) * 32, wn = (wid >> 2) * 64;

    float acc[2][8][4];
    #pragma unroll
    for (int i = 0; i < 2; i++)
        #pragma unroll
        for (int j = 0; j < 8; j++)
            #pragma unroll
            for (int e = 0; e < 4; e++) acc[i][j][e] = 0.f;

    auto LDST = [&](int c, int st) {
        const uint4* ag = Ap + ((size_t)blockIdx.y * NCH + c) * 8 * 128;
        const uint4* bg = Bp + ((size_t)blockIdx.x * NCH + c) * 8 * 128;
        const uint32_t ab = sbase + (uint32_t)(st * 2 * BSTAGE) * 16;
        const uint32_t bb = ab + (uint32_t)BSTAGE * 16;
        #pragma unroll
        for (int i = 0; i < 4; i++) {
            const int idx = t + i * 256;
            const int slot = idx >> 7, row = idx & 127;
            CP16(ab + (uint32_t)(slot * BRS + row) * 16, ag + idx);
            CP16(bb + (uint32_t)(slot * BRS + row) * 16, bg + idx);
        }
    };

    LDST(0, 0);
    CP_COMMIT();

    for (int c = 0; c < NCH; c++) {
        if (c + 1 < NCH) {
            LDST(c + 1, (c + 1) & 1);
            CP_COMMIT();
            CP_WAIT1();
        } else {
            CP_WAIT0();
        }
        __syncthreads();

        const uint4* As4 = sm4 + (c & 1) * 2 * BSTAGE;
        const uint4* Bs4 = As4 + BSTAGE;

        #pragma unroll
        for (int ks = 0; ks < 2; ks++) {
            uint4 A0[2], A8[2];
            #pragma unroll
            for (int tm = 0; tm < 2; tm++) {
                const int mr = wm + tm * 16 + qr;
                A0[tm] = As4[(ks * 4 + qc) * BRS + mr];
                A8[tm] = As4[(ks * 4 + qc) * BRS + mr + 8];
            }
            #pragma unroll
            for (int tn = 0; tn < 8; tn++) {
                const uint4 Bf = Bs4[(ks * 4 + qc) * BRS + wn + tn * 8 + qr];
                #pragma unroll
                for (int tm = 0; tm < 2; tm++) {
                    float* d = acc[tm][tn];
                    mma_bf16(d, A0[tm].x, A8[tm].x, A0[tm].y, A8[tm].y, Bf.x, Bf.y);
                    mma_bf16(d, A0[tm].x, A8[tm].x, A0[tm].y, A8[tm].y, Bf.z, Bf.w);
                    mma_bf16(d, A0[tm].z, A8[tm].z, A0[tm].w, A8[tm].w, Bf.x, Bf.y);
                }
            }
        }
        __syncthreads();
    }

    #pragma unroll
    for (int tm = 0; tm < 2; tm++) {
        const int r0 = m0 + wm + tm * 16 + qr;
        #pragma unroll
        for (int tn = 0; tn < 8; tn++) {
            const int col = n0 + wn + tn * 8 + qc * 2;
            const float bz0 = bias[col], bz1 = bias[col + 1];
            #pragma unroll
            for (int half = 0; half < 2; half++) {
                const int row = r0 + half * 8;
                const float v0 = acc[tm][tn][half * 2 + 0] + bz0;
                const float v1 = acc[tm][tn][half * 2 + 1] + bz1;
                if (mode == 0) {
                    const int bb = row >> 11, s = row & (SEQ - 1);
                    const int h = col / 192, r = col - h * 192;
                    const int part = r >> 6, dd = r & 63;
                    float* dst = (part == 0) ? g_q : (part == 1) ? g_k : g_v;
                    *(float2*)&dst[(((size_t)(bb * NH + h)) * SEQ + s) * HD + dd] =
                        make_float2(v0, v1);
                } else {
                    *(float2*)&outp[(size_t)row * DIM + col] = make_float2(v0, v1);
                }
            }
        }
    }
}

// ---------------------------------------------------------------------------
// prep_pack (unchanged from R7)
// ---------------------------------------------------------------------------
#define PSTAGE 68
#define PREP_SMEM (3*64*PSTAGE*(int)sizeof(float))

__global__ __launch_bounds__(256) void prep_pack() {
    extern __shared__ float ps[];
    float* Sq = ps;
    float* Sk = ps + 64*PSTAGE;
    float* Sv = ps + 2*64*PSTAGE;
    const int t = threadIdx.x;
    const int bh = blockIdx.y, s0 = blockIdx.x * 64;
    const size_t base = (size_t)bh * SEQ * HD;

    #pragma unroll
    for (int i = 0; i < 4; i++) {
        const int li = t + i * 256;
        const int row = li >> 4, c4 = (li & 15) << 2;
        const float4 q = *(const float4*)(g_q + base + (size_t)(s0 + row) * HD + c4);
        *(float4*)&Sq[row * PSTAGE + c4] = q;
        const float4 k = *(const float4*)(g_k + base + (size_t)(s0 + row) * HD + c4);
        *(float4*)&Sk[row * PSTAGE + c4] = k;
        float ss = fmaf(k.x, k.x, fmaf(k.y, k.y, fmaf(k.z, k.z, k.w * k.w)));
        #pragma unroll
        for (int off = 1; off <= 8; off <<= 1)
            ss += __shfl_xor_sync(0xffffffffu, ss, off);
        if ((t & 15) == 0)
            g_ksq[(size_t)bh * SEQ + s0 + row] = LOG2E * ss;
        const float4 v = *(const float4*)(g_v + base + (size_t)(s0 + row) * HD + c4);
        *(float4*)&Sv[row * PSTAGE + c4] = v;
    }
    __syncthreads();

    const size_t ob = ((size_t)bh * SEQ + s0) * 16;
    #pragma unroll
    for (int i = 0; i < 4; i++) {
        const int li = t + i * 256;
        const int r = li >> 4, slot = li & 15;
        const int ks = slot >> 2, q3 = slot & 3;
        const int c0 = ks * 16 + 2 * q3, c8 = c0 + 8;
        float h0, l0, h1, l1, h2, l2, h3, l3;
        bsplit(C2LE * Sq[r * PSTAGE + c0    ], h0, l0);
        bsplit(C2LE * Sq[r * PSTAGE + c0 + 1], h1, l1);
        bsplit(C2LE * Sq[r * PSTAGE + c8    ], h2, l2);
        bsplit(C2LE * Sq[r * PSTAGE + c8 + 1], h3, l3);
        g_qpb[ob + r * 16 + slot] =
            make_uint4(bpack(h0, h1), bpack(h2, h3), bpack(l0, l1), bpack(l2, l3));
        bsplit(Sk[r * PSTAGE + c0    ], h0, l0);
        bsplit(Sk[r * PSTAGE + c0 + 1], h1, l1);
        bsplit(Sk[r * PSTAGE + c8    ], h2, l2);
        bsplit(Sk[r * PSTAGE + c8 + 1], h3, l3);
        g_kqb[ob + r * 16 + slot] =
            make_uint4(bpack(h0, h1), bpack(h2, h3), bpack(l0, l1), bpack(l2, l3));
    }
    const size_t vb = ((size_t)bh * (SEQ / 2) + (s0 >> 1)) * 32;
    #pragma unroll
    for (int i = 0; i < 4; i++) {
        const int li = t + i * 256;
        const int r = li >> 5, slot4 = li & 31;
        const int a = (r >> 2) * 8 + (r & 3);
        const int d2 = slot4 * 2;
        ((float4*)g_vp)[vb + r * 32 + slot4] = make_float4(
            tf32f(Sv[a * PSTAGE + d2]),     tf32f(Sv[(a + 4) * PSTAGE + d2]),
            tf32f(Sv[a * PSTAGE + d2 + 1]), tf32f(Sv[(a + 4) * PSTAGE + d2 + 1]));
    }
}

// ---------------------------------------------------------------------------
// Flash attention v5: R7 body; epilogue writes g_attp packed bf16 hi/lo
// directly (out-projection consumes it with zero extra passes).
// ---------------------------------------------------------------------------
#define KB4S 20
#define KB_W (64*KB4S*4)
#define VP2S 84
#define VP_F (32*VP2S*2)
#define PSTR 68
#define FLASH_SMEM ((KB_W + VP_F + 64)*(int)sizeof(float))

__global__ __launch_bounds__(128, 3) void flash_mma() {
    extern __shared__ float s[];
    uint4*  Kb4  = (uint4*)s;
    float4* Vp4  = (float4*)(s + KB_W);
    float2* Vp2  = (float2*)(s + KB_W);
    float*  ksqs = s + KB_W + VP_F;
    float*  Ps   = s;

    const int t = threadIdx.x, lane = t & 31, w = t >> 5;
    const int qr = lane >> 2, qc = lane & 3;
    const int wm = w * 16;
    const int bh = blockIdx.y;
    const int s0 = blockIdx.x * 64;
    const size_t rbase = (size_t)bh * SEQ;

    uint32_t qh[4][4], ql[4][4];
    {
        const uint4* q0 = g_qpb + (rbase + s0 + wm + qr) * 16;
        const uint4* q1 = q0 + 8 * 16;
        #pragma unroll
        for (int ks = 0; ks < 4; ks++) {
            const uint4 f0 = q0[ks * 4 + qc];
            const uint4 f1 = q1[ks * 4 + qc];
            qh[ks][0] = f0.x; qh[ks][1] = f1.x; qh[ks][2] = f0.y; qh[ks][3] = f1.y;
            ql[ks][0] = f0.z; ql[ks][1] = f1.z; ql[ks][2] = f0.w; ql[ks][3] = f1.w;
        }
    }

    float oacc[8][4];
    #pragma unroll
    for (int tn = 0; tn < 8; tn++)
        #pragma unroll
        for (int e = 0; e < 4; e++) oacc[tn][e] = 0.f;
    float l0r = 0.f, l1r = 0.f;

    for (int t0 = 0; t0 < SEQ; t0 += 64) {
        __syncthreads();
        {
            const uint4* kg = g_kqb + (rbase + t0) * 16;
            #pragma unroll
            for (int i = 0; i < 8; i++) {
                const int li = t + i * 128;
                const int row = li >> 4, slot = li & 15;
                Kb4[row * KB4S + slot] = kg[row * 16 + slot];
            }
        }
        {
            const float4* vg = (const float4*)g_vp +
                               ((size_t)bh * (SEQ / 2) + (t0 >> 1)) * 32;
            #pragma unroll
            for (int i = 0; i < 8; i++) {
                const int li = t + i * 128;
                const int slot = li & 31, row = li >> 5;
                Vp4[row * (VP2S / 2) + slot] = vg[row * 32 + slot];
            }
        }
        if (t < 64) ksqs[t] = g_ksq[rbase + t0 + t];
        __syncthreads();

        float sacc[8][4];
        #pragma unroll
        for (int tn = 0; tn < 8; tn++)
            #pragma unroll
            for (int e = 0; e < 4; e++) sacc[tn][e] = 0.f;

        #pragma unroll
        for (int ks = 0; ks < 4; ks++) {
            #pragma unroll
            for (int tn = 0; tn < 8; tn++) {
                const uint4 wv = Kb4[(tn * 8 + qr) * KB4S + ks * 4 + qc];
                float* d = sacc[tn];
                mma_bf16(d, qh[ks][0], qh[ks][1], qh[ks][2], qh[ks][3], wv.x, wv.y);
                mma_bf16(d, qh[ks][0], qh[ks][1], qh[ks][2], qh[ks][3], wv.z, wv.w);
                mma_bf16(d, ql[ks][0], ql[ks][1], ql[ks][2], ql[ks][3], wv.x, wv.y);
            }
        }
        __syncthreads();

        const float2* ksq2 = (const float2*)ksqs;
        #pragma unroll
        for (int tn = 0; tn < 8; tn++) {
            const float2 kk = ksq2[tn * 4 + qc];
            const float p0 = tf32f(ex2f(sacc[tn][0] - kk.x));
            const float p1 = tf32f(ex2f(sacc[tn][1] - kk.y));
            const float p2 = tf32f(ex2f(sacc[tn][2] - kk.x));
            const float p3 = tf32f(ex2f(sacc[tn][3] - kk.y));
            l0r += p0 + p1;
            l1r += p2 + p3;
            *(float2*)&Ps[(wm + qr    ) * PSTR + tn * 8 + 2 * qc] = make_float2(p0, p1);
            *(float2*)&Ps[(wm + qr + 8) * PSTR + tn * 8 + 2 * qc] = make_float2(p2, p3);
        }
        __syncwarp();

        #pragma unroll
        for (int ks = 0; ks < 8; ks++) {
            const float* pp = Ps + (wm + qr) * PSTR + ks * 8 + qc;
            const uint32_t a0 = U(pp[0]);
            const uint32_t a1 = U(pp[8 * PSTR]);
            const uint32_t a2 = U(pp[4]);
            const uint32_t a3 = U(pp[8 * PSTR + 4]);
            #pragma unroll
            for (int tn = 0; tn < 8; tn++) {
                const float2 vv = Vp2[(ks * 4 + qc) * VP2S + tn * 8 + qr];
                mma_tf32(oacc[tn], a0, a1, a2, a3, U(vv.x), U(vv.y));
            }
        }
    }

    #pragma unroll
    for (int off = 1; off <= 2; off <<= 1) {
        l0r += __shfl_xor_sync(0xffffffffu, l0r, off);
        l1r += __shfl_xor_sync(0xffffffffu, l1r, off);
    }
    const float inv0 = 1.f / l0r, inv1 = 1.f / l1r;
    const int b = bh >> 4, h = bh & 15;

    // Packed epilogue: write g_attp[((mblk*NCH + c)*8 + s)*128 + r]
    #pragma unroll
    for (int half = 0; half < 2; half++) {
        const int m = b * SEQ + s0 + wm + qr + half * 8;
        const int mblk = m >> 7, r = m & 127;
        const float inv = half ? inv1 : inv0;
        const int e0 = half * 2;
        #pragma unroll
        for (int tn = 0; tn < 8; tn += 2) {
            const int g = tn * 8 + 2 * qc;
            const int cglob = 2 * h + (g >> 5);
            const int sslot = ((g >> 4) & 1) * 4 + qc;
            float h0, l0, h1, l1, h2, l2, h3, l3;
            bsplit(oacc[tn    ][e0    ] * inv, h0, l0);
            bsplit(oacc[tn    ][e0 + 1] * inv, h1, l1);
            bsplit(oacc[tn + 1][e0    ] * inv, h2, l2);
            bsplit(oacc[tn + 1][e0 + 1] * inv, h3, l3);
            g_attp[((size_t)mblk * NCH + cglob) * 8 * 128 + sslot * 128 + r] =
                make_uint4(bpack(h0, h1), bpack(h2, h3), bpack(l0, l1), bpack(l2, l3));
        }
    }
}

// ---------------------------------------------------------------------------
extern "C" void kernel_launch(void* const* d_in, const int* in_sizes, int n_in,
                              void* d_out, int out_size) {
    (void)in_sizes; (void)n_in; (void)out_size;
    const float* x    = (const float*)d_in[0];
    const float* Wqkv = (const float*)d_in[1];
    const float* bqkv = (const float*)d_in[2];
    const float* Wo   = (const float*)d_in[3];
    const float* bo   = (const float*)d_in[4];
    float*       out  = (float*)d_out;

    uint4* xp;   cudaGetSymbolAddress((void**)&xp,   g_xp);
    uint4* attp; cudaGetSymbolAddress((void**)&attp, g_attp);
    uint4* wqp;  cudaGetSymbolAddress((void**)&wqp,  g_wqp);
    uint4* wop;  cudaGetSymbolAddress((void**)&wop,  g_wop);

    cudaFuncSetAttribute(bf16_gemm, cudaFuncAttributeMaxDynamicSharedMemorySize, GSMEM2);
    cudaFuncSetAttribute(prep_pack, cudaFuncAttributeMaxDynamicSharedMemorySize, PREP_SMEM);
    cudaFuncSetAttribute(flash_mma, cudaFuncAttributeMaxDynamicSharedMemorySize, FLASH_SMEM);

    pack_w<<<dim3(N_QKV/128, NCH), 256>>>(Wqkv, wqp, N_QKV);
    pack_w<<<dim3(DIM/128,  NCH), 256>>>(Wo,   wop, DIM);
    pack_x<<<dim3(M_ROWS/128, NCH), 256>>>(x, xp);

    bf16_gemm<<<dim3(N_QKV/128, M_ROWS/128), 256, GSMEM2>>>(xp, wqp, bqkv, nullptr, 0);

    prep_pack<<<dim3(SEQ/64, NUM_B*NH), 256, PREP_SMEM>>>();

    flash_mma<<<dim3(SEQ/64, NUM_B*NH), 128, FLASH_SMEM>>>();

    bf16_gemm<<<dim3(DIM/128, M_ROWS/128), 256, GSMEM2>>>(attp, wop, bo, out, 1);
}

// round 10
// speedup vs baseline: 2.5116x; 1.1165x over previous
#include <cuda_runtime.h>
#include <cuda_bf16.h>
#include <cuda_fp16.h>
#include <cstdint>

#define NUM_B 2
#define SEQ   2048
#define DIM   1024
#define NH    16
#define HD    64
#define M_ROWS (NUM_B*SEQ)
#define N_QKV  (3*DIM)
#define KDIM   DIM
#define NCH    (KDIM/32)

#define LOG2E 1.4426950408889634f
#define C2LE  2.8853900817779268f

// Scratch
__device__ float g_q  [(size_t)NUM_B*NH*SEQ*HD];
__device__ float g_k  [(size_t)NUM_B*NH*SEQ*HD];
__device__ float g_v  [(size_t)NUM_B*NH*SEQ*HD];
// bf16 hi/lo fragment-packed GEMM operands
__device__ uint4 g_xp  [(size_t)M_ROWS*256];
__device__ uint4 g_attp[(size_t)M_ROWS*256];
__device__ uint4 g_wqp [(size_t)N_QKV*256];
__device__ uint4 g_wop [(size_t)DIM*256];
// flash operands
__device__ uint4    g_qpb[(size_t)NUM_B*NH*SEQ*16];
__device__ uint4    g_kqb[(size_t)NUM_B*NH*SEQ*16];
__device__ uint32_t g_vph[(size_t)NUM_B*NH*SEQ*32];   // fp16 key-paired V
__device__ float    g_ksq[(size_t)NUM_B*NH*SEQ];

// ---------------------------------------------------------------------------
// Helpers
// ---------------------------------------------------------------------------
__device__ __forceinline__ float ex2f(float x) {
    float r;
    asm("ex2.approx.f32 %0, %1;" : "=f"(r) : "f"(x));
    return r;
}
__device__ __forceinline__ void bsplit(float x, float& h, float& l) {
    h = __bfloat162float(__float2bfloat16_rn(x));
    l = x - h;
}
__device__ __forceinline__ uint32_t bpack(float a, float b) {
    __nv_bfloat162 t = __floats2bfloat162_rn(a, b);
    return *(uint32_t*)&t;
}
__device__ __forceinline__ uint32_t hpack(float a, float b) {
    __half2 t = __floats2half2_rn(a, b);
    return *(uint32_t*)&t;
}
__device__ __forceinline__ void mma_bf16(float* d,
                                         uint32_t a0, uint32_t a1, uint32_t a2, uint32_t a3,
                                         uint32_t b0, uint32_t b1) {
    asm volatile(
        "mma.sync.aligned.m16n8k16.row.col.f32.bf16.bf16.f32 "
        "{%0,%1,%2,%3}, {%4,%5,%6,%7}, {%8,%9}, {%0,%1,%2,%3};"
        : "+f"(d[0]), "+f"(d[1]), "+f"(d[2]), "+f"(d[3])
        : "r"(a0), "r"(a1), "r"(a2), "r"(a3), "r"(b0), "r"(b1));
}
__device__ __forceinline__ void mma_f16(float* d,
                                        uint32_t a0, uint32_t a1, uint32_t a2, uint32_t a3,
                                        uint32_t b0, uint32_t b1) {
    asm volatile(
        "mma.sync.aligned.m16n8k16.row.col.f32.f16.f16.f32 "
        "{%0,%1,%2,%3}, {%4,%5,%6,%7}, {%8,%9}, {%0,%1,%2,%3};"
        : "+f"(d[0]), "+f"(d[1]), "+f"(d[2]), "+f"(d[3])
        : "r"(a0), "r"(a1), "r"(a2), "r"(a3), "r"(b0), "r"(b1));
}
#define U(x) __float_as_uint(x)
#define CP16(dst, src) \
    asm volatile("cp.async.cg.shared.global [%0], [%1], 16;" :: "r"(dst), "l"(src))
#define CP_COMMIT() asm volatile("cp.async.commit_group;" ::: "memory")
#define CP_WAIT1()  asm volatile("cp.async.wait_group 1;" ::: "memory")
#define CP_WAIT0()  asm volatile("cp.async.wait_group 0;" ::: "memory")
__device__ __forceinline__ uint32_t smem_u32(const void* p) {
    uint32_t a;
    asm("{ .reg .u64 t; cvta.to.shared.u64 t, %1; cvt.u32.u64 %0, t; }"
        : "=r"(a) : "l"(p));
    return a;
}

// ---------------------------------------------------------------------------
// pack_w / pack_x (unchanged)
// ---------------------------------------------------------------------------
__global__ __launch_bounds__(256) void pack_w(const float* __restrict__ W,
                                              uint4* __restrict__ outp, int N) {
    __shared__ float Sw[32 * 136];
    const int t = threadIdx.x;
    const int n0 = blockIdx.x * 128, k0 = blockIdx.y * 32;
    #pragma unroll
    for (int i = 0; i < 4; i++) {
        const int idx = t + i * 256;
        const int kr = idx >> 5, c4 = (idx & 31) * 4;
        *(float4*)&Sw[kr * 136 + c4] =
            *(const float4*)(W + (size_t)(k0 + kr) * N + n0 + c4);
    }
    __syncthreads();
    const size_t ob = ((size_t)blockIdx.x * NCH + blockIdx.y) * 8 * 128;
    #pragma unroll
    for (int i = 0; i < 4; i++) {
        const int idx = t + i * 256;
        const int s = idx >> 7, r = idx & 127;
        const int c0 = (s >> 2) * 16 + 2 * (s & 3), c8 = c0 + 8;
        float h0, l0, h1, l1, h2, l2, h3, l3;
        bsplit(Sw[(c0    ) * 136 + r], h0, l0);
        bsplit(Sw[(c0 + 1) * 136 + r], h1, l1);
        bsplit(Sw[(c8    ) * 136 + r], h2, l2);
        bsplit(Sw[(c8 + 1) * 136 + r], h3, l3);
        outp[ob + s * 128 + r] =
            make_uint4(bpack(h0, h1), bpack(h2, h3), bpack(l0, l1), bpack(l2, l3));
    }
}

__global__ __launch_bounds__(256) void pack_x(const float* __restrict__ A,
                                              uint4* __restrict__ outp) {
    __shared__ float Sx[128 * 36];
    const int t = threadIdx.x;
    const int m0 = blockIdx.x * 128, k0 = blockIdx.y * 32;
    #pragma unroll
    for (int i = 0; i < 4; i++) {
        const int idx = t + i * 256;
        const int row = idx >> 3, c4 = (idx & 7) * 4;
        *(float4*)&Sx[row * 36 + c4] =
            *(const float4*)(A + (size_t)(m0 + row) * KDIM + k0 + c4);
    }
    __syncthreads();
    const size_t ob = ((size_t)blockIdx.x * NCH + blockIdx.y) * 8 * 128;
    #pragma unroll
    for (int i = 0; i < 4; i++) {
        const int idx = t + i * 256;
        const int s = idx >> 7, r = idx & 127;
        const int c0 = (s >> 2) * 16 + 2 * (s & 3), c8 = c0 + 8;
        float h0, l0, h1, l1, h2, l2, h3, l3;
        bsplit(Sx[r * 36 + c0    ], h0, l0);
        bsplit(Sx[r * 36 + c0 + 1], h1, l1);
        bsplit(Sx[r * 36 + c8    ], h2, l2);
        bsplit(Sx[r * 36 + c8 + 1], h3, l3);
        outp[ob + s * 128 + r] =
            make_uint4(bpack(h0, h1), bpack(h2, h3), bpack(l0, l1), bpack(l2, l3));
    }
}

// ---------------------------------------------------------------------------
// 3xBF16 GEMM (R9 unroll-by-2 version)
// ---------------------------------------------------------------------------
#define BRS    130
#define BSTAGE (8*BRS)
#define GSMEM2 (2*2*BSTAGE*16)

__global__ __launch_bounds__(256) void bf16_gemm(
    const uint4* __restrict__ Ap,
    const uint4* __restrict__ Bp,
    const float* __restrict__ bias,
    float* __restrict__ outp, int mode)
{
    extern __shared__ uint4 sm4[];
    const uint32_t sbase = smem_u32(sm4);
    const int t = threadIdx.x, wid = t >> 5, lane = t & 31;
    const int qr = lane >> 2, qc = lane & 3;
    const int m0 = blockIdx.y * 128, n0 = blockIdx.x * 128;
    const int wm = (wid & 3) * 32, wn = (wid >> 2) * 64;

    float acc[2][8][4];
    #pragma unroll
    for (int i = 0; i < 2; i++)
        #pragma unroll
        for (int j = 0; j < 8; j++)
            #pragma unroll
            for (int e = 0; e < 4; e++) acc[i][j][e] = 0.f;

    auto LDST = [&](int c, int st) {
        const uint4* ag = Ap + ((size_t)blockIdx.y * NCH + c) * 8 * 128;
        const uint4* bg = Bp + ((size_t)blockIdx.x * NCH + c) * 8 * 128;
        const uint32_t ab = sbase + (uint32_t)(st * 2 * BSTAGE) * 16;
        const uint32_t bb = ab + (uint32_t)BSTAGE * 16;
        #pragma unroll
        for (int i = 0; i < 4; i++) {
            const int idx = t + i * 256;
            const int slot = idx >> 7, row = idx & 127;
            CP16(ab + (uint32_t)(slot * BRS + row) * 16, ag + idx);
            CP16(bb + (uint32_t)(slot * BRS + row) * 16, bg + idx);
        }
    };
    auto COMPUTE = [&](const uint4* __restrict__ As4, const uint4* __restrict__ Bs4) {
        #pragma unroll
        for (int ks = 0; ks < 2; ks++) {
            uint4 A0[2], A8[2];
            #pragma unroll
            for (int tm = 0; tm < 2; tm++) {
                const int mr = wm + tm * 16 + qr;
                A0[tm] = As4[(ks * 4 + qc) * BRS + mr];
                A8[tm] = As4[(ks * 4 + qc) * BRS + mr + 8];
            }
            #pragma unroll
            for (int tn = 0; tn < 8; tn++) {
                const uint4 Bf = Bs4[(ks * 4 + qc) * BRS + wn + tn * 8 + qr];
                #pragma unroll
                for (int tm = 0; tm < 2; tm++) {
                    float* d = acc[tm][tn];
                    mma_bf16(d, A0[tm].x, A8[tm].x, A0[tm].y, A8[tm].y, Bf.x, Bf.y);
                    mma_bf16(d, A0[tm].x, A8[tm].x, A0[tm].y, A8[tm].y, Bf.z, Bf.w);
                    mma_bf16(d, A0[tm].z, A8[tm].z, A0[tm].w, A8[tm].w, Bf.x, Bf.y);
                }
            }
        }
    };

    LDST(0, 0);
    CP_COMMIT();

    #pragma unroll 1
    for (int c = 0; c < NCH; c += 2) {
        if (c + 1 < NCH) { LDST(c + 1, 1); CP_COMMIT(); CP_WAIT1(); }
        else             { CP_WAIT0(); }
        __syncthreads();
        COMPUTE(sm4, sm4 + BSTAGE);
        __syncthreads();
        if (c + 2 < NCH) { LDST(c + 2, 0); CP_COMMIT(); CP_WAIT1(); }
        else             { CP_WAIT0(); }
        __syncthreads();
        COMPUTE(sm4 + 2 * BSTAGE, sm4 + 3 * BSTAGE);
        __syncthreads();
    }

    #pragma unroll
    for (int tm = 0; tm < 2; tm++) {
        const int r0 = m0 + wm + tm * 16 + qr;
        #pragma unroll
        for (int tn = 0; tn < 8; tn++) {
            const int col = n0 + wn + tn * 8 + qc * 2;
            const float bz0 = bias[col], bz1 = bias[col + 1];
            #pragma unroll
            for (int half = 0; half < 2; half++) {
                const int row = r0 + half * 8;
                const float v0 = acc[tm][tn][half * 2 + 0] + bz0;
                const float v1 = acc[tm][tn][half * 2 + 1] + bz1;
                if (mode == 0) {
                    const int bb = row >> 11, s = row & (SEQ - 1);
                    const int h = col / 192, r = col - h * 192;
                    const int part = r >> 6, dd = r & 63;
                    float* dst = (part == 0) ? g_q : (part == 1) ? g_k : g_v;
                    *(float2*)&dst[(((size_t)(bb * NH + h)) * SEQ + s) * HD + dd] =
                        make_float2(v0, v1);
                } else {
                    *(float2*)&outp[(size_t)row * DIM + col] = make_float2(v0, v1);
                }
            }
        }
    }
}

// ---------------------------------------------------------------------------
// prep_pack (unchanged from R9)
// ---------------------------------------------------------------------------
#define PSTAGE 68
#define PREP_SMEM (3*64*PSTAGE*(int)sizeof(float))

__global__ __launch_bounds__(256) void prep_pack() {
    extern __shared__ float ps[];
    float* Sq = ps;
    float* Sk = ps + 64*PSTAGE;
    float* Sv = ps + 2*64*PSTAGE;
    const int t = threadIdx.x;
    const int bh = blockIdx.y, s0 = blockIdx.x * 64;
    const size_t base = (size_t)bh * SEQ * HD;

    #pragma unroll
    for (int i = 0; i < 4; i++) {
        const int li = t + i * 256;
        const int row = li >> 4, c4 = (li & 15) << 2;
        const float4 q = *(const float4*)(g_q + base + (size_t)(s0 + row) * HD + c4);
        *(float4*)&Sq[row * PSTAGE + c4] = q;
        const float4 k = *(const float4*)(g_k + base + (size_t)(s0 + row) * HD + c4);
        *(float4*)&Sk[row * PSTAGE + c4] = k;
        float ss = fmaf(k.x, k.x, fmaf(k.y, k.y, fmaf(k.z, k.z, k.w * k.w)));
        #pragma unroll
        for (int off = 1; off <= 8; off <<= 1)
            ss += __shfl_xor_sync(0xffffffffu, ss, off);
        if ((t & 15) == 0)
            g_ksq[(size_t)bh * SEQ + s0 + row] = LOG2E * ss;
        const float4 v = *(const float4*)(g_v + base + (size_t)(s0 + row) * HD + c4);
        *(float4*)&Sv[row * PSTAGE + c4] = v;
    }
    __syncthreads();

    const size_t ob = ((size_t)bh * SEQ + s0) * 16;
    #pragma unroll
    for (int i = 0; i < 4; i++) {
        const int li = t + i * 256;
        const int r = li >> 4, slot = li & 15;
        const int ks = slot >> 2, q3 = slot & 3;
        const int c0 = ks * 16 + 2 * q3, c8 = c0 + 8;
        float h0, l0, h1, l1, h2, l2, h3, l3;
        bsplit(C2LE * Sq[r * PSTAGE + c0    ], h0, l0);
        bsplit(C2LE * Sq[r * PSTAGE + c0 + 1], h1, l1);
        bsplit(C2LE * Sq[r * PSTAGE + c8    ], h2, l2);
        bsplit(C2LE * Sq[r * PSTAGE + c8 + 1], h3, l3);
        g_qpb[ob + r * 16 + slot] =
            make_uint4(bpack(h0, h1), bpack(h2, h3), bpack(l0, l1), bpack(l2, l3));
        bsplit(Sk[r * PSTAGE + c0    ], h0, l0);
        bsplit(Sk[r * PSTAGE + c0 + 1], h1, l1);
        bsplit(Sk[r * PSTAGE + c8    ], h2, l2);
        bsplit(Sk[r * PSTAGE + c8 + 1], h3, l3);
        g_kqb[ob + r * 16 + slot] =
            make_uint4(bpack(h0, h1), bpack(h2, h3), bpack(l0, l1), bpack(l2, l3));
    }

    const size_t vb = ((size_t)bh * (SEQ / 64) + (s0 >> 6)) * 2048;
    #pragma unroll
    for (int i = 0; i < 8; i++) {
        const int idx = t + i * 256;
        const int row = idx >> 7;
        const int rem = idx & 127;
        const int d = rem >> 1, which = rem & 1;
        const int ks = row >> 2, qcq = row & 3;
        const int p = ks * 8 + qcq + 4 * which;
        g_vph[vb + idx] = hpack(Sv[(2 * p) * PSTAGE + d], Sv[(2 * p + 1) * PSTAGE + d]);
    }
}

// ---------------------------------------------------------------------------
// Flash attention v7: QK^T 3xBF16; PV fp16 register-fed with ONLINE ROW MAX
// (p = ex2(s - ksq - m) in (0,1] -> fp16-safe; l >= 1 -> no div-by-zero).
// ---------------------------------------------------------------------------
#define KB4S 20
#define KB_W (64*KB4S*4)
#define VST  136
#define VH_W (16*VST)
#define FLASH_SMEM ((KB_W + VH_W + 64)*(int)sizeof(float))

__global__ __launch_bounds__(128, 3) void flash_mma() {
    extern __shared__ float s[];
    uint4*    Kb4  = (uint4*)s;
    uint32_t* Vh   = (uint32_t*)s + KB_W;
    float*    ksqs = s + KB_W + VH_W;

    const int t = threadIdx.x, lane = t & 31, w = t >> 5;
    const int qr = lane >> 2, qc = lane & 3;
    const int wm = w * 16;
    const int bh = blockIdx.y;
    const int s0 = blockIdx.x * 64;
    const size_t rbase = (size_t)bh * SEQ;

    uint32_t qh[4][4], ql[4][4];
    {
        const uint4* q0 = g_qpb + (rbase + s0 + wm + qr) * 16;
        const uint4* q1 = q0 + 8 * 16;
        #pragma unroll
        for (int ks = 0; ks < 4; ks++) {
            const uint4 f0 = q0[ks * 4 + qc];
            const uint4 f1 = q1[ks * 4 + qc];
            qh[ks][0] = f0.x; qh[ks][1] = f1.x; qh[ks][2] = f0.y; qh[ks][3] = f1.y;
            ql[ks][0] = f0.z; ql[ks][1] = f1.z; ql[ks][2] = f0.w; ql[ks][3] = f1.w;
        }
    }

    float oacc[8][4];
    #pragma unroll
    for (int tn = 0; tn < 8; tn++)
        #pragma unroll
        for (int e = 0; e < 4; e++) oacc[tn][e] = 0.f;
    float m0r = -1e30f, m1r = -1e30f, l0r = 0.f, l1r = 0.f;

    for (int t0 = 0; t0 < SEQ; t0 += 64) {
        __syncthreads();
        {
            const uint4* kg = g_kqb + (rbase + t0) * 16;
            #pragma unroll
            for (int i = 0; i < 8; i++) {
                const int li = t + i * 128;
                const int row = li >> 4, slot = li & 15;
                Kb4[row * KB4S + slot] = kg[row * 16 + slot];
            }
        }
        {
            const uint4* vg = (const uint4*)g_vph +
                              ((size_t)bh * (SEQ / 64) + (t0 >> 6)) * 512;
            #pragma unroll
            for (int i = 0; i < 4; i++) {
                const int li = t + i * 128;
                const int row = li >> 5, rem = (li & 31) * 4;
                *(uint4*)&Vh[row * VST + rem] = vg[li];
            }
        }
        if (t < 64) ksqs[t] = g_ksq[rbase + t0 + t];
        __syncthreads();

        // S = (2c*Q).K^T — 3xBF16
        float sacc[8][4];
        #pragma unroll
        for (int tn = 0; tn < 8; tn++)
            #pragma unroll
            for (int e = 0; e < 4; e++) sacc[tn][e] = 0.f;

        #pragma unroll
        for (int ks = 0; ks < 4; ks++) {
            #pragma unroll
            for (int tn = 0; tn < 8; tn++) {
                const uint4 wv = Kb4[(tn * 8 + qr) * KB4S + ks * 4 + qc];
                float* d = sacc[tn];
                mma_bf16(d, qh[ks][0], qh[ks][1], qh[ks][2], qh[ks][3], wv.x, wv.y);
                mma_bf16(d, qh[ks][0], qh[ks][1], qh[ks][2], qh[ks][3], wv.z, wv.w);
                mma_bf16(d, ql[ks][0], ql[ks][1], ql[ks][2], ql[ks][3], wv.x, wv.y);
            }
        }

        // logits (log2-units) = sacc - ksq; online row max
        float mx0 = -1e30f, mx1 = -1e30f;
        const float2* ksq2 = (const float2*)ksqs;
        #pragma unroll
        for (int tn = 0; tn < 8; tn++) {
            const float2 kk = ksq2[tn * 4 + qc];
            sacc[tn][0] -= kk.x; sacc[tn][1] -= kk.y;
            sacc[tn][2] -= kk.x; sacc[tn][3] -= kk.y;
            mx0 = fmaxf(mx0, fmaxf(sacc[tn][0], sacc[tn][1]));
            mx1 = fmaxf(mx1, fmaxf(sacc[tn][2], sacc[tn][3]));
        }
        #pragma unroll
        for (int off = 1; off <= 2; off <<= 1) {
            mx0 = fmaxf(mx0, __shfl_xor_sync(0xffffffffu, mx0, off));
            mx1 = fmaxf(mx1, __shfl_xor_sync(0xffffffffu, mx1, off));
        }
        const float mn0 = fmaxf(m0r, mx0), mn1 = fmaxf(m1r, mx1);
        const float al0 = ex2f(m0r - mn0), al1 = ex2f(m1r - mn1);
        m0r = mn0; m1r = mn1;

        float rs0 = 0.f, rs1 = 0.f;
        #pragma unroll
        for (int tn = 0; tn < 8; tn++) {
            sacc[tn][0] = ex2f(sacc[tn][0] - mn0);
            sacc[tn][1] = ex2f(sacc[tn][1] - mn0);
            sacc[tn][2] = ex2f(sacc[tn][2] - mn1);
            sacc[tn][3] = ex2f(sacc[tn][3] - mn1);
            rs0 += sacc[tn][0] + sacc[tn][1];
            rs1 += sacc[tn][2] + sacc[tn][3];
            oacc[tn][0] *= al0; oacc[tn][1] *= al0;
            oacc[tn][2] *= al1; oacc[tn][3] *= al1;
        }
        l0r = l0r * al0 + rs0;
        l1r = l1r * al1 + rs1;

        // PV fp16, A-fragments direct from registers (p in (0,1])
        #pragma unroll
        for (int ks = 0; ks < 4; ks++) {
            const uint32_t a0 = hpack(sacc[2*ks    ][0], sacc[2*ks    ][1]);
            const uint32_t a1 = hpack(sacc[2*ks    ][2], sacc[2*ks    ][3]);
            const uint32_t a2 = hpack(sacc[2*ks + 1][0], sacc[2*ks + 1][1]);
            const uint32_t a3 = hpack(sacc[2*ks + 1][2], sacc[2*ks + 1][3]);
            #pragma unroll
            for (int tn = 0; tn < 8; tn++) {
                const uint2 b01 =
                    *(const uint2*)&Vh[(ks * 4 + qc) * VST + (tn * 8 + qr) * 2];
                mma_f16(oacc[tn], a0, a1, a2, a3, b01.x, b01.y);
            }
        }
    }

    #pragma unroll
    for (int off = 1; off <= 2; off <<= 1) {
        l0r += __shfl_xor_sync(0xffffffffu, l0r, off);
        l1r += __shfl_xor_sync(0xffffffffu, l1r, off);
    }
    const float inv0 = 1.f / l0r, inv1 = 1.f / l1r;
    const int b = bh >> 4, h = bh & 15;

    #pragma unroll
    for (int half = 0; half < 2; half++) {
        const int m = b * SEQ + s0 + wm + qr + half * 8;
        const int mblk = m >> 7, r = m & 127;
        const float inv = half ? inv1 : inv0;
        const int e0 = half * 2;
        #pragma unroll
        for (int tn = 0; tn < 8; tn += 2) {
            const int g = tn * 8 + 2 * qc;
            const int cglob = 2 * h + (g >> 5);
            const int sslot = ((g >> 4) & 1) * 4 + qc;
            float h0, l0, h1, l1, h2, l2, h3, l3;
            bsplit(oacc[tn    ][e0    ] * inv, h0, l0);
            bsplit(oacc[tn    ][e0 + 1] * inv, h1, l1);
            bsplit(oacc[tn + 1][e0    ] * inv, h2, l2);
            bsplit(oacc[tn + 1][e0 + 1] * inv, h3, l3);
            g_attp[((size_t)mblk * NCH + cglob) * 8 * 128 + sslot * 128 + r] =
                make_uint4(bpack(h0, h1), bpack(h2, h3), bpack(l0, l1), bpack(l2, l3));
        }
    }
}

// ---------------------------------------------------------------------------
extern "C" void kernel_launch(void* const* d_in, const int* in_sizes, int n_in,
                              void* d_out, int out_size) {
    (void)in_sizes; (void)n_in; (void)out_size;
    const float* x    = (const float*)d_in[0];
    const float* Wqkv = (const float*)d_in[1];
    const float* bqkv = (const float*)d_in[2];
    const float* Wo   = (const float*)d_in[3];
    const float* bo   = (const float*)d_in[4];
    float*       out  = (float*)d_out;

    uint4* xp;   cudaGetSymbolAddress((void**)&xp,   g_xp);
    uint4* attp; cudaGetSymbolAddress((void**)&attp, g_attp);
    uint4* wqp;  cudaGetSymbolAddress((void**)&wqp,  g_wqp);
    uint4* wop;  cudaGetSymbolAddress((void**)&wop,  g_wop);

    cudaFuncSetAttribute(bf16_gemm, cudaFuncAttributeMaxDynamicSharedMemorySize, GSMEM2);
    cudaFuncSetAttribute(prep_pack, cudaFuncAttributeMaxDynamicSharedMemorySize, PREP_SMEM);
    cudaFuncSetAttribute(flash_mma, cudaFuncAttributeMaxDynamicSharedMemorySize, FLASH_SMEM);

    pack_w<<<dim3(N_QKV/128, NCH), 256>>>(Wqkv, wqp, N_QKV);
    pack_w<<<dim3(DIM/128,  NCH), 256>>>(Wo,   wop, DIM);
    pack_x<<<dim3(M_ROWS/128, NCH), 256>>>(x, xp);

    bf16_gemm<<<dim3(N_QKV/128, M_ROWS/128), 256, GSMEM2>>>(xp, wqp, bqkv, nullptr, 0);

    prep_pack<<<dim3(SEQ/64, NUM_B*NH), 256, PREP_SMEM>>>();

    flash_mma<<<dim3(SEQ/64, NUM_B*NH), 128, FLASH_SMEM>>>();

    bf16_gemm<<<dim3(DIM/128, M_ROWS/128), 256, GSMEM2>>>(attp, wop, bo, out, 1);
}

// round 11
// speedup vs baseline: 2.5186x; 1.0028x over previous
#include <cuda_runtime.h>
#include <cuda_bf16.h>
#include <cuda_fp16.h>
#include <cstdint>

#define NUM_B 2
#define SEQ   2048
#define DIM   1024
#define NH    16
#define HD    64
#define M_ROWS (NUM_B*SEQ)
#define N_QKV  (3*DIM)
#define KDIM   DIM
#define NCH    (KDIM/32)

#define LOG2E 1.4426950408889634f
#define C2LE  2.8853900817779268f

// Scratch
__device__ float g_q  [(size_t)NUM_B*NH*SEQ*HD];
__device__ float g_k  [(size_t)NUM_B*NH*SEQ*HD];
__device__ float g_v  [(size_t)NUM_B*NH*SEQ*HD];
// bf16 hi/lo fragment-packed GEMM operands
__device__ uint4 g_xp  [(size_t)M_ROWS*256];
__device__ uint4 g_attp[(size_t)M_ROWS*256];
__device__ uint4 g_wqp [(size_t)N_QKV*256];
__device__ uint4 g_wop [(size_t)DIM*256];
// flash operands
__device__ uint4    g_qpb[(size_t)NUM_B*NH*SEQ*16];
__device__ uint4    g_kqb[(size_t)NUM_B*NH*SEQ*16];
__device__ uint32_t g_vph[(size_t)NUM_B*NH*SEQ*32];
__device__ float    g_ksq[(size_t)NUM_B*NH*SEQ];

// ---------------------------------------------------------------------------
// Helpers
// ---------------------------------------------------------------------------
__device__ __forceinline__ float ex2f(float x) {
    float r;
    asm("ex2.approx.f32 %0, %1;" : "=f"(r) : "f"(x));
    return r;
}
__device__ __forceinline__ void bsplit(float x, float& h, float& l) {
    h = __bfloat162float(__float2bfloat16_rn(x));
    l = x - h;
}
__device__ __forceinline__ uint32_t bpack(float a, float b) {
    __nv_bfloat162 t = __floats2bfloat162_rn(a, b);
    return *(uint32_t*)&t;
}
__device__ __forceinline__ uint32_t hpack(float a, float b) {
    __half2 t = __floats2half2_rn(a, b);
    return *(uint32_t*)&t;
}
__device__ __forceinline__ void mma_bf16(float* d,
                                         uint32_t a0, uint32_t a1, uint32_t a2, uint32_t a3,
                                         uint32_t b0, uint32_t b1) {
    asm volatile(
        "mma.sync.aligned.m16n8k16.row.col.f32.bf16.bf16.f32 "
        "{%0,%1,%2,%3}, {%4,%5,%6,%7}, {%8,%9}, {%0,%1,%2,%3};"
        : "+f"(d[0]), "+f"(d[1]), "+f"(d[2]), "+f"(d[3])
        : "r"(a0), "r"(a1), "r"(a2), "r"(a3), "r"(b0), "r"(b1));
}
__device__ __forceinline__ void mma_f16(float* d,
                                        uint32_t a0, uint32_t a1, uint32_t a2, uint32_t a3,
                                        uint32_t b0, uint32_t b1) {
    asm volatile(
        "mma.sync.aligned.m16n8k16.row.col.f32.f16.f16.f32 "
        "{%0,%1,%2,%3}, {%4,%5,%6,%7}, {%8,%9}, {%0,%1,%2,%3};"
        : "+f"(d[0]), "+f"(d[1]), "+f"(d[2]), "+f"(d[3])
        : "r"(a0), "r"(a1), "r"(a2), "r"(a3), "r"(b0), "r"(b1));
}
#define U(x) __float_as_uint(x)
#define CP16(dst, src) \
    asm volatile("cp.async.cg.shared.global [%0], [%1], 16;" :: "r"(dst), "l"(src))
#define CP_COMMIT() asm volatile("cp.async.commit_group;" ::: "memory")
#define CP_WAIT1()  asm volatile("cp.async.wait_group 1;" ::: "memory")
#define CP_WAIT0()  asm volatile("cp.async.wait_group 0;" ::: "memory")
__device__ __forceinline__ uint32_t smem_u32(const void* p) {
    uint32_t a;
    asm("{ .reg .u64 t; cvta.to.shared.u64 t, %1; cvt.u32.u64 %0, t; }"
        : "=r"(a) : "l"(p));
    return a;
}

// ---------------------------------------------------------------------------
// pack_w / pack_x (unchanged)
// ---------------------------------------------------------------------------
__global__ __launch_bounds__(256) void pack_w(const float* __restrict__ W,
                                              uint4* __restrict__ outp, int N) {
    __shared__ float Sw[32 * 136];
    const int t = threadIdx.x;
    const int n0 = blockIdx.x * 128, k0 = blockIdx.y * 32;
    #pragma unroll
    for (int i = 0; i < 4; i++) {
        const int idx = t + i * 256;
        const int kr = idx >> 5, c4 = (idx & 31) * 4;
        *(float4*)&Sw[kr * 136 + c4] =
            *(const float4*)(W + (size_t)(k0 + kr) * N + n0 + c4);
    }
    __syncthreads();
    const size_t ob = ((size_t)blockIdx.x * NCH + blockIdx.y) * 8 * 128;
    #pragma unroll
    for (int i = 0; i < 4; i++) {
        const int idx = t + i * 256;
        const int s = idx >> 7, r = idx & 127;
        const int c0 = (s >> 2) * 16 + 2 * (s & 3), c8 = c0 + 8;
        float h0, l0, h1, l1, h2, l2, h3, l3;
        bsplit(Sw[(c0    ) * 136 + r], h0, l0);
        bsplit(Sw[(c0 + 1) * 136 + r], h1, l1);
        bsplit(Sw[(c8    ) * 136 + r], h2, l2);
        bsplit(Sw[(c8 + 1) * 136 + r], h3, l3);
        outp[ob + s * 128 + r] =
            make_uint4(bpack(h0, h1), bpack(h2, h3), bpack(l0, l1), bpack(l2, l3));
    }
}

__global__ __launch_bounds__(256) void pack_x(const float* __restrict__ A,
                                              uint4* __restrict__ outp) {
    __shared__ float Sx[128 * 36];
    const int t = threadIdx.x;
    const int m0 = blockIdx.x * 128, k0 = blockIdx.y * 32;
    #pragma unroll
    for (int i = 0; i < 4; i++) {
        const int idx = t + i * 256;
        const int row = idx >> 3, c4 = (idx & 7) * 4;
        *(float4*)&Sx[row * 36 + c4] =
            *(const float4*)(A + (size_t)(m0 + row) * KDIM + k0 + c4);
    }
    __syncthreads();
    const size_t ob = ((size_t)blockIdx.x * NCH + blockIdx.y) * 8 * 128;
    #pragma unroll
    for (int i = 0; i < 4; i++) {
        const int idx = t + i * 256;
        const int s = idx >> 7, r = idx & 127;
        const int c0 = (s >> 2) * 16 + 2 * (s & 3), c8 = c0 + 8;
        float h0, l0, h1, l1, h2, l2, h3, l3;
        bsplit(Sx[r * 36 + c0    ], h0, l0);
        bsplit(Sx[r * 36 + c0 + 1], h1, l1);
        bsplit(Sx[r * 36 + c8    ], h2, l2);
        bsplit(Sx[r * 36 + c8 + 1], h3, l3);
        outp[ob + s * 128 + r] =
            make_uint4(bpack(h0, h1), bpack(h2, h3), bpack(l0, l1), bpack(l2, l3));
    }
}

// ---------------------------------------------------------------------------
// 3xBF16 GEMM v3: 4 warps/CTA, warp tile 64x64 (4 m-tiles x 8 n-tiles),
// MMA:LDS = 6. Same packed layout/CTA tile as v2.
// ---------------------------------------------------------------------------
#define BRS    130
#define BSTAGE (8*BRS)
#define GSMEM2 (2*2*BSTAGE*16)

__global__ __launch_bounds__(128, 2) void bf16_gemm(
    const uint4* __restrict__ Ap,
    const uint4* __restrict__ Bp,
    const float* __restrict__ bias,
    float* __restrict__ outp, int mode)
{
    extern __shared__ uint4 sm4[];
    const uint32_t sbase = smem_u32(sm4);
    const int t = threadIdx.x, wid = t >> 5, lane = t & 31;
    const int qr = lane >> 2, qc = lane & 3;
    const int m0 = blockIdx.y * 128, n0 = blockIdx.x * 128;
    const int wm = (wid & 1) * 64, wn = (wid >> 1) * 64;

    float acc[4][8][4];
    #pragma unroll
    for (int i = 0; i < 4; i++)
        #pragma unroll
        for (int j = 0; j < 8; j++)
            #pragma unroll
            for (int e = 0; e < 4; e++) acc[i][j][e] = 0.f;

    auto LDST = [&](int c, int st) {
        const uint4* ag = Ap + ((size_t)blockIdx.y * NCH + c) * 8 * 128;
        const uint4* bg = Bp + ((size_t)blockIdx.x * NCH + c) * 8 * 128;
        const uint32_t ab = sbase + (uint32_t)(st * 2 * BSTAGE) * 16;
        const uint32_t bb = ab + (uint32_t)BSTAGE * 16;
        #pragma unroll
        for (int i = 0; i < 8; i++) {
            const int idx = t + i * 128;
            const int slot = idx >> 7, row = idx & 127;
            CP16(ab + (uint32_t)(slot * BRS + row) * 16, ag + idx);
            CP16(bb + (uint32_t)(slot * BRS + row) * 16, bg + idx);
        }
    };
    auto COMPUTE = [&](const uint4* __restrict__ As4, const uint4* __restrict__ Bs4) {
        #pragma unroll
        for (int ks = 0; ks < 2; ks++) {
            uint4 A0[4], A8[4];
            #pragma unroll
            for (int tm = 0; tm < 4; tm++) {
                const int mr = wm + tm * 16 + qr;
                A0[tm] = As4[(ks * 4 + qc) * BRS + mr];
                A8[tm] = As4[(ks * 4 + qc) * BRS + mr + 8];
            }
            #pragma unroll
            for (int tn = 0; tn < 8; tn++) {
                const uint4 Bf = Bs4[(ks * 4 + qc) * BRS + wn + tn * 8 + qr];
                #pragma unroll
                for (int tm = 0; tm < 4; tm++) {
                    float* d = acc[tm][tn];
                    mma_bf16(d, A0[tm].x, A8[tm].x, A0[tm].y, A8[tm].y, Bf.x, Bf.y);
                    mma_bf16(d, A0[tm].x, A8[tm].x, A0[tm].y, A8[tm].y, Bf.z, Bf.w);
                    mma_bf16(d, A0[tm].z, A8[tm].z, A0[tm].w, A8[tm].w, Bf.x, Bf.y);
                }
            }
        }
    };

    LDST(0, 0);
    CP_COMMIT();

    #pragma unroll 1
    for (int c = 0; c < NCH; c += 2) {
        if (c + 1 < NCH) { LDST(c + 1, 1); CP_COMMIT(); CP_WAIT1(); }
        else             { CP_WAIT0(); }
        __syncthreads();
        COMPUTE(sm4, sm4 + BSTAGE);
        __syncthreads();
        if (c + 2 < NCH) { LDST(c + 2, 0); CP_COMMIT(); CP_WAIT1(); }
        else             { CP_WAIT0(); }
        __syncthreads();
        COMPUTE(sm4 + 2 * BSTAGE, sm4 + 3 * BSTAGE);
        __syncthreads();
    }

    #pragma unroll
    for (int tm = 0; tm < 4; tm++) {
        const int r0 = m0 + wm + tm * 16 + qr;
        #pragma unroll
        for (int tn = 0; tn < 8; tn++) {
            const int col = n0 + wn + tn * 8 + qc * 2;
            const float bz0 = bias[col], bz1 = bias[col + 1];
            #pragma unroll
            for (int half = 0; half < 2; half++) {
                const int row = r0 + half * 8;
                const float v0 = acc[tm][tn][half * 2 + 0] + bz0;
                const float v1 = acc[tm][tn][half * 2 + 1] + bz1;
                if (mode == 0) {
                    const int bb = row >> 11, s = row & (SEQ - 1);
                    const int h = col / 192, r = col - h * 192;
                    const int part = r >> 6, dd = r & 63;
                    float* dst = (part == 0) ? g_q : (part == 1) ? g_k : g_v;
                    *(float2*)&dst[(((size_t)(bb * NH + h)) * SEQ + s) * HD + dd] =
                        make_float2(v0, v1);
                } else {
                    *(float2*)&outp[(size_t)row * DIM + col] = make_float2(v0, v1);
                }
            }
        }
    }
}

// ---------------------------------------------------------------------------
// prep_pack (unchanged)
// ---------------------------------------------------------------------------
#define PSTAGE 68
#define PREP_SMEM (3*64*PSTAGE*(int)sizeof(float))

__global__ __launch_bounds__(256) void prep_pack() {
    extern __shared__ float ps[];
    float* Sq = ps;
    float* Sk = ps + 64*PSTAGE;
    float* Sv = ps + 2*64*PSTAGE;
    const int t = threadIdx.x;
    const int bh = blockIdx.y, s0 = blockIdx.x * 64;
    const size_t base = (size_t)bh * SEQ * HD;

    #pragma unroll
    for (int i = 0; i < 4; i++) {
        const int li = t + i * 256;
        const int row = li >> 4, c4 = (li & 15) << 2;
        const float4 q = *(const float4*)(g_q + base + (size_t)(s0 + row) * HD + c4);
        *(float4*)&Sq[row * PSTAGE + c4] = q;
        const float4 k = *(const float4*)(g_k + base + (size_t)(s0 + row) * HD + c4);
        *(float4*)&Sk[row * PSTAGE + c4] = k;
        float ss = fmaf(k.x, k.x, fmaf(k.y, k.y, fmaf(k.z, k.z, k.w * k.w)));
        #pragma unroll
        for (int off = 1; off <= 8; off <<= 1)
            ss += __shfl_xor_sync(0xffffffffu, ss, off);
        if ((t & 15) == 0)
            g_ksq[(size_t)bh * SEQ + s0 + row] = LOG2E * ss;
        const float4 v = *(const float4*)(g_v + base + (size_t)(s0 + row) * HD + c4);
        *(float4*)&Sv[row * PSTAGE + c4] = v;
    }
    __syncthreads();

    const size_t ob = ((size_t)bh * SEQ + s0) * 16;
    #pragma unroll
    for (int i = 0; i < 4; i++) {
        const int li = t + i * 256;
        const int r = li >> 4, slot = li & 15;
        const int ks = slot >> 2, q3 = slot & 3;
        const int c0 = ks * 16 + 2 * q3, c8 = c0 + 8;
        float h0, l0, h1, l1, h2, l2, h3, l3;
        bsplit(C2LE * Sq[r * PSTAGE + c0    ], h0, l0);
        bsplit(C2LE * Sq[r * PSTAGE + c0 + 1], h1, l1);
        bsplit(C2LE * Sq[r * PSTAGE + c8    ], h2, l2);
        bsplit(C2LE * Sq[r * PSTAGE + c8 + 1], h3, l3);
        g_qpb[ob + r * 16 + slot] =
            make_uint4(bpack(h0, h1), bpack(h2, h3), bpack(l0, l1), bpack(l2, l3));
        bsplit(Sk[r * PSTAGE + c0    ], h0, l0);
        bsplit(Sk[r * PSTAGE + c0 + 1], h1, l1);
        bsplit(Sk[r * PSTAGE + c8    ], h2, l2);
        bsplit(Sk[r * PSTAGE + c8 + 1], h3, l3);
        g_kqb[ob + r * 16 + slot] =
            make_uint4(bpack(h0, h1), bpack(h2, h3), bpack(l0, l1), bpack(l2, l3));
    }

    const size_t vb = ((size_t)bh * (SEQ / 64) + (s0 >> 6)) * 2048;
    #pragma unroll
    for (int i = 0; i < 8; i++) {
        const int idx = t + i * 256;
        const int row = idx >> 7;
        const int rem = idx & 127;
        const int d = rem >> 1, which = rem & 1;
        const int ks = row >> 2, qcq = row & 3;
        const int p = ks * 8 + qcq + 4 * which;
        g_vph[vb + idx] = hpack(Sv[(2 * p) * PSTAGE + d], Sv[(2 * p + 1) * PSTAGE + d]);
    }
}

// ---------------------------------------------------------------------------
// Flash attention v7 (unchanged from R10 — known-good)
// ---------------------------------------------------------------------------
#define KB4S 20
#define KB_W (64*KB4S*4)
#define VST  136
#define VH_W (16*VST)
#define FLASH_SMEM ((KB_W + VH_W + 64)*(int)sizeof(float))

__global__ __launch_bounds__(128, 3) void flash_mma() {
    extern __shared__ float s[];
    uint4*    Kb4  = (uint4*)s;
    uint32_t* Vh   = (uint32_t*)s + KB_W;
    float*    ksqs = s + KB_W + VH_W;

    const int t = threadIdx.x, lane = t & 31, w = t >> 5;
    const int qr = lane >> 2, qc = lane & 3;
    const int wm = w * 16;
    const int bh = blockIdx.y;
    const int s0 = blockIdx.x * 64;
    const size_t rbase = (size_t)bh * SEQ;

    uint32_t qh[4][4], ql[4][4];
    {
        const uint4* q0 = g_qpb + (rbase + s0 + wm + qr) * 16;
        const uint4* q1 = q0 + 8 * 16;
        #pragma unroll
        for (int ks = 0; ks < 4; ks++) {
            const uint4 f0 = q0[ks * 4 + qc];
            const uint4 f1 = q1[ks * 4 + qc];
            qh[ks][0] = f0.x; qh[ks][1] = f1.x; qh[ks][2] = f0.y; qh[ks][3] = f1.y;
            ql[ks][0] = f0.z; ql[ks][1] = f1.z; ql[ks][2] = f0.w; ql[ks][3] = f1.w;
        }
    }

    float oacc[8][4];
    #pragma unroll
    for (int tn = 0; tn < 8; tn++)
        #pragma unroll
        for (int e = 0; e < 4; e++) oacc[tn][e] = 0.f;
    float m0r = -1e30f, m1r = -1e30f, l0r = 0.f, l1r = 0.f;

    for (int t0 = 0; t0 < SEQ; t0 += 64) {
        __syncthreads();
        {
            const uint4* kg = g_kqb + (rbase + t0) * 16;
            #pragma unroll
            for (int i = 0; i < 8; i++) {
                const int li = t + i * 128;
                const int row = li >> 4, slot = li & 15;
                Kb4[row * KB4S + slot] = kg[row * 16 + slot];
            }
        }
        {
            const uint4* vg = (const uint4*)g_vph +
                              ((size_t)bh * (SEQ / 64) + (t0 >> 6)) * 512;
            #pragma unroll
            for (int i = 0; i < 4; i++) {
                const int li = t + i * 128;
                const int row = li >> 5, rem = (li & 31) * 4;
                *(uint4*)&Vh[row * VST + rem] = vg[li];
            }
        }
        if (t < 64) ksqs[t] = g_ksq[rbase + t0 + t];
        __syncthreads();

        float sacc[8][4];
        #pragma unroll
        for (int tn = 0; tn < 8; tn++)
            #pragma unroll
            for (int e = 0; e < 4; e++) sacc[tn][e] = 0.f;

        #pragma unroll
        for (int ks = 0; ks < 4; ks++) {
            #pragma unroll
            for (int tn = 0; tn < 8; tn++) {
                const uint4 wv = Kb4[(tn * 8 + qr) * KB4S + ks * 4 + qc];
                float* d = sacc[tn];
                mma_bf16(d, qh[ks][0], qh[ks][1], qh[ks][2], qh[ks][3], wv.x, wv.y);
                mma_bf16(d, qh[ks][0], qh[ks][1], qh[ks][2], qh[ks][3], wv.z, wv.w);
                mma_bf16(d, ql[ks][0], ql[ks][1], ql[ks][2], ql[ks][3], wv.x, wv.y);
            }
        }

        float mx0 = -1e30f, mx1 = -1e30f;
        const float2* ksq2 = (const float2*)ksqs;
        #pragma unroll
        for (int tn = 0; tn < 8; tn++) {
            const float2 kk = ksq2[tn * 4 + qc];
            sacc[tn][0] -= kk.x; sacc[tn][1] -= kk.y;
            sacc[tn][2] -= kk.x; sacc[tn][3] -= kk.y;
            mx0 = fmaxf(mx0, fmaxf(sacc[tn][0], sacc[tn][1]));
            mx1 = fmaxf(mx1, fmaxf(sacc[tn][2], sacc[tn][3]));
        }
        #pragma unroll
        for (int off = 1; off <= 2; off <<= 1) {
            mx0 = fmaxf(mx0, __shfl_xor_sync(0xffffffffu, mx0, off));
            mx1 = fmaxf(mx1, __shfl_xor_sync(0xffffffffu, mx1, off));
        }
        const float mn0 = fmaxf(m0r, mx0), mn1 = fmaxf(m1r, mx1);
        const float al0 = ex2f(m0r - mn0), al1 = ex2f(m1r - mn1);
        m0r = mn0; m1r = mn1;

        float rs0 = 0.f, rs1 = 0.f;
        #pragma unroll
        for (int tn = 0; tn < 8; tn++) {
            sacc[tn][0] = ex2f(sacc[tn][0] - mn0);
            sacc[tn][1] = ex2f(sacc[tn][1] - mn0);
            sacc[tn][2] = ex2f(sacc[tn][2] - mn1);
            sacc[tn][3] = ex2f(sacc[tn][3] - mn1);
            rs0 += sacc[tn][0] + sacc[tn][1];
            rs1 += sacc[tn][2] + sacc[tn][3];
            oacc[tn][0] *= al0; oacc[tn][1] *= al0;
            oacc[tn][2] *= al1; oacc[tn][3] *= al1;
        }
        l0r = l0r * al0 + rs0;
        l1r = l1r * al1 + rs1;

        #pragma unroll
        for (int ks = 0; ks < 4; ks++) {
            const uint32_t a0 = hpack(sacc[2*ks    ][0], sacc[2*ks    ][1]);
            const uint32_t a1 = hpack(sacc[2*ks    ][2], sacc[2*ks    ][3]);
            const uint32_t a2 = hpack(sacc[2*ks + 1][0], sacc[2*ks + 1][1]);
            const uint32_t a3 = hpack(sacc[2*ks + 1][2], sacc[2*ks + 1][3]);
            #pragma unroll
            for (int tn = 0; tn < 8; tn++) {
                const uint2 b01 =
                    *(const uint2*)&Vh[(ks * 4 + qc) * VST + (tn * 8 + qr) * 2];
                mma_f16(oacc[tn], a0, a1, a2, a3, b01.x, b01.y);
            }
        }
    }

    #pragma unroll
    for (int off = 1; off <= 2; off <<= 1) {
        l0r += __shfl_xor_sync(0xffffffffu, l0r, off);
        l1r += __shfl_xor_sync(0xffffffffu, l1r, off);
    }
    const float inv0 = 1.f / l0r, inv1 = 1.f / l1r;
    const int b = bh >> 4, h = bh & 15;

    #pragma unroll
    for (int half = 0; half < 2; half++) {
        const int m = b * SEQ + s0 + wm + qr + half * 8;
        const int mblk = m >> 7, r = m & 127;
        const float inv = half ? inv1 : inv0;
        const int e0 = half * 2;
        #pragma unroll
        for (int tn = 0; tn < 8; tn += 2) {
            const int g = tn * 8 + 2 * qc;
            const int cglob = 2 * h + (g >> 5);
            const int sslot = ((g >> 4) & 1) * 4 + qc;
            float h0, l0, h1, l1, h2, l2, h3, l3;
            bsplit(oacc[tn    ][e0    ] * inv, h0, l0);
            bsplit(oacc[tn    ][e0 + 1] * inv, h1, l1);
            bsplit(oacc[tn + 1][e0    ] * inv, h2, l2);
            bsplit(oacc[tn + 1][e0 + 1] * inv, h3, l3);
            g_attp[((size_t)mblk * NCH + cglob) * 8 * 128 + sslot * 128 + r] =
                make_uint4(bpack(h0, h1), bpack(h2, h3), bpack(l0, l1), bpack(l2, l3));
        }
    }
}

// ---------------------------------------------------------------------------
extern "C" void kernel_launch(void* const* d_in, const int* in_sizes, int n_in,
                              void* d_out, int out_size) {
    (void)in_sizes; (void)n_in; (void)out_size;
    const float* x    = (const float*)d_in[0];
    const float* Wqkv = (const float*)d_in[1];
    const float* bqkv = (const float*)d_in[2];
    const float* Wo   = (const float*)d_in[3];
    const float* bo   = (const float*)d_in[4];
    float*       out  = (float*)d_out;

    uint4* xp;   cudaGetSymbolAddress((void**)&xp,   g_xp);
    uint4* attp; cudaGetSymbolAddress((void**)&attp, g_attp);
    uint4* wqp;  cudaGetSymbolAddress((void**)&wqp,  g_wqp);
    uint4* wop;  cudaGetSymbolAddress((void**)&wop,  g_wop);

    cudaFuncSetAttribute(bf16_gemm, cudaFuncAttributeMaxDynamicSharedMemorySize, GSMEM2);
    cudaFuncSetAttribute(prep_pack, cudaFuncAttributeMaxDynamicSharedMemorySize, PREP_SMEM);
    cudaFuncSetAttribute(flash_mma, cudaFuncAttributeMaxDynamicSharedMemorySize, FLASH_SMEM);

    pack_w<<<dim3(N_QKV/128, NCH), 256>>>(Wqkv, wqp, N_QKV);
    pack_w<<<dim3(DIM/128,  NCH), 256>>>(Wo,   wop, DIM);
    pack_x<<<dim3(M_ROWS/128, NCH), 256>>>(x, xp);

    bf16_gemm<<<dim3(N_QKV/128, M_ROWS/128), 128, GSMEM2>>>(xp, wqp, bqkv, nullptr, 0);

    prep_pack<<<dim3(SEQ/64, NUM_B*NH), 256, PREP_SMEM>>>();

    flash_mma<<<dim3(SEQ/64, NUM_B*NH), 128, FLASH_SMEM>>>();

    bf16_gemm<<<dim3(DIM/128, M_ROWS/128), 128, GSMEM2>>>(attp, wop, bo, out, 1);
}